// round 4
// baseline (speedup 1.0000x reference)
#include <cuda_runtime.h>
#include <math.h>

#define N_NODES 8000
#define N_EDGES 64000
#define E_TOT   (N_EDGES + N_NODES)   /* 72000 with self loops */
#define HEADS   8
#define OUT_C   512
#define HC      (HEADS * OUT_C)       /* 4096 */
#define IN_C    128
#define LIN_OUT 512
#define NEG_SLOPE 0.2f
#define EPS_F   1e-16f

/* ------------- scratch (static device globals; no allocation) ------------- */
__device__ float g_h[(size_t)N_NODES * HC];      /* 131 MB */
__device__ float g_agg[(size_t)N_NODES * HC];    /* 131 MB */
__device__ float g_asrc[N_NODES * HEADS];
__device__ float g_adst[N_NODES * HEADS];
__device__ int   g_count[N_NODES];
__device__ int   g_cursor[N_NODES];
__device__ int   g_off[N_NODES + 1];
__device__ int   g_csr_src[E_TOT];
__device__ float g_alpha[(size_t)E_TOT * HEADS];
__device__ float g_bias2[LIN_OUT];
__device__ int   g_is64;   /* 1 if edge_index is int64, 0 if int32 */

/* -------- edge_index dtype detection: int64 little-endian with values
 * < N_NODES has ALL odd 32-bit words == 0; int32 data has random indices
 * there. Sample 64 odd words -> misdetection probability ~ 8000^-64. -------- */
__global__ void k_detect(const int* __restrict__ ei32) {
    int lane = threadIdx.x;             /* 64 threads */
    int w = ei32[2 * lane + 1];
    unsigned any = __ballot_sync(0xFFFFFFFFu, w != 0);
    __shared__ int s_any;
    if (threadIdx.x == 0) s_any = 0;
    __syncthreads();
    if (any && (lane & 31) == 0) atomicOr(&s_any, 1);
    __syncthreads();
    if (threadIdx.x == 0) g_is64 = (s_any == 0) ? 1 : 0;
}

/* decode edge i -> (src,dst); returns 0 if out of range (skip, no trap) */
__device__ __forceinline__ int edge_decode(const int* ei32, int i, int& src, int& dst) {
    if (i >= N_EDGES) { src = dst = i - N_EDGES; return 1; }  /* self loop */
    if (g_is64) {
        src = ei32[2 * i];                      /* low word of int64 */
        dst = ei32[2 * (N_EDGES + i)];
    } else {
        src = ei32[i];
        dst = ei32[N_EDGES + i];
    }
    return (src >= 0 && src < N_NODES && dst >= 0 && dst < N_NODES);
}

/* ---------------------------- init ---------------------------- */
__global__ void k_init(const float* __restrict__ b_lin) {
    int i = blockIdx.x * blockDim.x + threadIdx.x;
    if (i < N_NODES) { g_count[i] = 0; g_cursor[i] = 0; }
    if (i < LIN_OUT) g_bias2[i] = b_lin[i];
}

/* ---------------------------- CSR build ---------------------------- */
__global__ void k_hist(const int* __restrict__ ei32) {
    int i = blockIdx.x * blockDim.x + threadIdx.x;
    if (i >= E_TOT) return;
    int src, dst;
    if (edge_decode(ei32, i, src, dst))
        atomicAdd(&g_count[dst], 1);
}

__global__ void k_scan() {
    __shared__ int s[1024];
    int tid = threadIdx.x;
    int carry = 0;
    for (int c = 0; c < 8; c++) {
        int idx = c * 1024 + tid;
        int v = (idx < N_NODES) ? g_count[idx] : 0;
        s[tid] = v;
        __syncthreads();
        for (int d = 1; d < 1024; d <<= 1) {
            int t = (tid >= d) ? s[tid - d] : 0;
            __syncthreads();
            s[tid] += t;
            __syncthreads();
        }
        if (idx <= N_NODES) g_off[idx] = carry + s[tid] - v;  /* exclusive */
        int tot = s[1023];
        __syncthreads();
        carry += tot;
    }
}

__global__ void k_scatter(const int* __restrict__ ei32) {
    int i = blockIdx.x * blockDim.x + threadIdx.x;
    if (i >= E_TOT) return;
    int src, dst;
    if (!edge_decode(ei32, i, src, dst)) return;
    int pos = g_off[dst] + atomicAdd(&g_cursor[dst], 1);
    g_csr_src[pos] = src;
}

/* ---------------------------- SGEMM 128x128x8 ----------------------------
 * MODE 0: g_h = A @ B          (A,B kernel args)
 * MODE 1: Cout = g_agg @ B + g_bias2
 * Global scratch bound in DEVICE code only. */
template <int MODE>
__global__ __launch_bounds__(256)
void sgemm128(const float* __restrict__ Ain, const float* __restrict__ B,
              float* __restrict__ Cout, int M, int N, int K) {
    const float* A = (MODE == 1) ? (const float*)g_agg : Ain;
    float* C = (MODE == 0) ? (float*)g_h : Cout;

    const int BM = 128, BN = 128, BK = 8;
    __shared__ float As[BK][BM];
    __shared__ float Bs[BK][BN];

    int tid = threadIdx.x;
    int tx = tid & 15;
    int ty = tid >> 4;
    int row0 = blockIdx.y * BM;
    int col0 = blockIdx.x * BN;

    int aRow = tid >> 1;
    int aCol = (tid & 1) * 4;
    int bRow = tid >> 5;
    int bCol = (tid & 31) * 4;

    float acc[8][8];
#pragma unroll
    for (int i = 0; i < 8; i++)
#pragma unroll
        for (int j = 0; j < 8; j++) acc[i][j] = 0.f;

    for (int k0 = 0; k0 < K; k0 += BK) {
        float4 av = make_float4(0.f, 0.f, 0.f, 0.f);
        if (row0 + aRow < M)
            av = *(const float4*)(A + (size_t)(row0 + aRow) * K + k0 + aCol);
        As[aCol + 0][aRow] = av.x;
        As[aCol + 1][aRow] = av.y;
        As[aCol + 2][aRow] = av.z;
        As[aCol + 3][aRow] = av.w;

        float4 bv = *(const float4*)(B + (size_t)(k0 + bRow) * N + col0 + bCol);
        *(float4*)&Bs[bRow][bCol] = bv;
        __syncthreads();

#pragma unroll
        for (int kk = 0; kk < BK; kk++) {
            float4 a0 = *(const float4*)&As[kk][ty * 8];
            float4 a1 = *(const float4*)&As[kk][ty * 8 + 4];
            float4 b0 = *(const float4*)&Bs[kk][tx * 8];
            float4 b1 = *(const float4*)&Bs[kk][tx * 8 + 4];
            float ra[8] = {a0.x, a0.y, a0.z, a0.w, a1.x, a1.y, a1.z, a1.w};
            float rb[8] = {b0.x, b0.y, b0.z, b0.w, b1.x, b1.y, b1.z, b1.w};
#pragma unroll
            for (int i = 0; i < 8; i++)
#pragma unroll
                for (int j = 0; j < 8; j++) acc[i][j] += ra[i] * rb[j];
        }
        __syncthreads();
    }

#pragma unroll
    for (int i = 0; i < 8; i++) {
        int r = row0 + ty * 8 + i;
        if (r < M) {
            float* cp = C + (size_t)r * N + col0 + tx * 8;
#pragma unroll
            for (int j = 0; j < 8; j++) {
                float v = acc[i][j];
                if (MODE == 1) v += g_bias2[col0 + tx * 8 + j];
                cp[j] = v;
            }
        }
    }
}

/* ---------------------- per-node attention logits ---------------------- */
__global__ void k_att(const float* __restrict__ att_src,
                      const float* __restrict__ att_dst) {
    int n = blockIdx.x;
    int w = threadIdx.x >> 5;
    int lane = threadIdx.x & 31;
    const float* hrow = g_h + (size_t)n * HC + w * OUT_C;
    const float* as = att_src + w * OUT_C;
    const float* ad = att_dst + w * OUT_C;
    float s = 0.f, d = 0.f;
    for (int c = lane; c < OUT_C; c += 32) {
        float hv = hrow[c];
        s += hv * as[c];
        d += hv * ad[c];
    }
#pragma unroll
    for (int o = 16; o; o >>= 1) {
        s += __shfl_xor_sync(0xFFFFFFFFu, s, o);
        d += __shfl_xor_sync(0xFFFFFFFFu, d, o);
    }
    if (lane == 0) {
        g_asrc[n * HEADS + w] = s;
        g_adst[n * HEADS + w] = d;
    }
}

/* ---------------------- edge softmax (one warp per dst node) ---------------------- */
__global__ void k_softmax() {
    int gwarp = (blockIdx.x * blockDim.x + threadIdx.x) >> 5;
    int lane = threadIdx.x & 31;
    if (gwarp >= N_NODES) return;
    int beg = g_off[gwarp], end = g_off[gwarp + 1];
    for (int h = 0; h < HEADS; h++) {
        float ad = g_adst[gwarp * HEADS + h];
        float m = -1e30f;
        for (int e = beg + lane; e < end; e += 32) {
            float v = g_asrc[g_csr_src[e] * HEADS + h] + ad;
            v = v > 0.f ? v : NEG_SLOPE * v;
            m = fmaxf(m, v);
        }
#pragma unroll
        for (int o = 16; o; o >>= 1) m = fmaxf(m, __shfl_xor_sync(0xFFFFFFFFu, m, o));
        float s = 0.f;
        for (int e = beg + lane; e < end; e += 32) {
            float v = g_asrc[g_csr_src[e] * HEADS + h] + ad;
            v = v > 0.f ? v : NEG_SLOPE * v;
            s += expf(v - m);
        }
#pragma unroll
        for (int o = 16; o; o >>= 1) s += __shfl_xor_sync(0xFFFFFFFFu, s, o);
        float inv = 1.f / (s + EPS_F);
        for (int e = beg + lane; e < end; e += 32) {
            float v = g_asrc[g_csr_src[e] * HEADS + h] + ad;
            v = v > 0.f ? v : NEG_SLOPE * v;
            g_alpha[(size_t)e * HEADS + h] = expf(v - m) * inv;
        }
    }
}

/* ---------------------- aggregation (gather, one block per dst) ---------------------- */
__global__ __launch_bounds__(512) void k_agg() {
    int n = blockIdx.x;
    int t = threadIdx.x;
    float acc[HEADS];
#pragma unroll
    for (int j = 0; j < HEADS; j++) acc[j] = 0.f;
    int beg = g_off[n], end = g_off[n + 1];
    for (int s = beg; s < end; s++) {
        int src = g_csr_src[s];
        const float* hrow = g_h + (size_t)src * HC;
        const float* al = g_alpha + (size_t)s * HEADS;
#pragma unroll
        for (int j = 0; j < HEADS; j++)
            acc[j] += al[j] * hrow[j * OUT_C + t];
    }
    float* out = g_agg + (size_t)n * HC;
#pragma unroll
    for (int j = 0; j < HEADS; j++) out[j * OUT_C + t] = acc[j];
}

/* ---------------------- fused bias2 = b_lin + b_gat @ W_lin ---------------------- */
__global__ void k_bias2(const float* __restrict__ b_gat,
                        const float* __restrict__ W_lin) {
    int t = threadIdx.x;
    int k0 = blockIdx.x * 128;
    float acc = 0.f;
    for (int k = k0; k < k0 + 128; k++)
        acc += b_gat[k] * W_lin[(size_t)k * LIN_OUT + t];
    atomicAdd(&g_bias2[t], acc);
}

/* ---------------------------- launch ---------------------------- */
extern "C" void kernel_launch(void* const* d_in, const int* in_sizes, int n_in,
                              void* d_out, int out_size) {
    const float* x       = (const float*)d_in[0];
    const int*   ei32    = (const int*)d_in[1];   /* dtype auto-detected */
    const float* W_gat   = (const float*)d_in[2];
    const float* b_gat   = (const float*)d_in[3];
    const float* att_src = (const float*)d_in[4];
    const float* att_dst = (const float*)d_in[5];
    const float* W_lin   = (const float*)d_in[6];
    const float* b_lin   = (const float*)d_in[7];
    float* out = (float*)d_out;

    k_detect<<<1, 64>>>(ei32);
    k_init<<<(N_NODES + 255) / 256, 256>>>(b_lin);
    k_hist<<<(E_TOT + 255) / 256, 256>>>(ei32);
    k_scan<<<1, 1024>>>();
    k_scatter<<<(E_TOT + 255) / 256, 256>>>(ei32);
    k_bias2<<<32, LIN_OUT>>>(b_gat, W_lin);

    /* GEMM1: g_h = x @ W_gat   (8000 x 128 x 4096) */
    {
        dim3 grid(HC / 128, (N_NODES + 127) / 128);
        sgemm128<0><<<grid, 256>>>(x, W_gat, nullptr, N_NODES, HC, IN_C);
    }

    k_att<<<N_NODES, 256>>>(att_src, att_dst);
    k_softmax<<<(N_NODES * 32 + 255) / 256, 256>>>();
    k_agg<<<N_NODES, 512>>>();

    /* GEMM2: out = g_agg @ W_lin + g_bias2   (8000 x 4096 x 512) */
    {
        dim3 grid(LIN_OUT / 128, (N_NODES + 127) / 128);
        sgemm128<1><<<grid, 256>>>(nullptr, W_lin, out, N_NODES, LIN_OUT, HC);
    }
}

// round 7
// speedup vs baseline: 1.7713x; 1.7713x over previous
#include <cuda_runtime.h>
#include <cuda_bf16.h>
#include <math.h>
#include <stdint.h>

#define N_NODES 8000
#define M_PAD   8064                  /* 63 * 128 */
#define N_EDGES 64000
#define E_TOT   (N_EDGES + N_NODES)
#define HEADS   8
#define OUT_C   512
#define HC      (HEADS * OUT_C)       /* 4096 */
#define IN_C    128
#define LIN_OUT 512
#define NEG_SLOPE 0.2f
#define EPS_F   1e-16f

/* ------------- scratch (static device globals; no allocation) ------------- */
__device__ float g_h[(size_t)N_NODES * HC];
__device__ __nv_bfloat16 g_xhi[(size_t)M_PAD * IN_C];
__device__ __nv_bfloat16 g_xlo[(size_t)M_PAD * IN_C];
__device__ __nv_bfloat16 g_wgat_hi[(size_t)HC * IN_C];    /* W_gat^T [4096,128] */
__device__ __nv_bfloat16 g_wgat_lo[(size_t)HC * IN_C];
__device__ __nv_bfloat16 g_agghi[(size_t)M_PAD * HC];
__device__ __nv_bfloat16 g_agglo[(size_t)M_PAD * HC];
__device__ __nv_bfloat16 g_wlin_hi[(size_t)LIN_OUT * HC]; /* W_lin^T [512,4096] */
__device__ __nv_bfloat16 g_wlin_lo[(size_t)LIN_OUT * HC];
__device__ float g_asrc[N_NODES * HEADS];
__device__ float g_adst[N_NODES * HEADS];
__device__ int   g_count[N_NODES];
__device__ int   g_cursor[N_NODES];
__device__ int   g_off[N_NODES + 1];
__device__ int   g_csr_src[E_TOT];
__device__ float g_alpha[(size_t)E_TOT * HEADS];
__device__ float g_bias2[LIN_OUT];
__device__ int   g_is64;

/* ============================ PTX helpers (family-safe) ============================ */
__device__ __forceinline__ uint32_t smem_u32(const void* p) {
    uint32_t a;
    asm("{ .reg .u64 t; cvta.to.shared.u64 t, %1; cvt.u32.u64 %0, t; }"
        : "=r"(a) : "l"(p));
    return a;
}
__device__ __forceinline__ void cp_async16(uint32_t s, const void* g) {
    asm volatile("cp.async.cg.shared.global [%0], [%1], 16;" :: "r"(s), "l"(g));
}
__device__ __forceinline__ void cp_commit() {
    asm volatile("cp.async.commit_group;" ::: "memory");
}
template <int N>
__device__ __forceinline__ void cp_wait() {
    asm volatile("cp.async.wait_group %0;" :: "n"(N) : "memory");
}
__device__ __forceinline__ void ldm_x4(uint32_t addr, uint32_t& r0, uint32_t& r1,
                                       uint32_t& r2, uint32_t& r3) {
    asm volatile("ldmatrix.sync.aligned.m8n8.x4.shared.b16 {%0,%1,%2,%3}, [%4];"
                 : "=r"(r0), "=r"(r1), "=r"(r2), "=r"(r3) : "r"(addr));
}
__device__ __forceinline__ void mma_bf16(float& c0, float& c1, float& c2, float& c3,
                                         uint32_t a0, uint32_t a1, uint32_t a2, uint32_t a3,
                                         uint32_t b0, uint32_t b1) {
    asm volatile(
        "mma.sync.aligned.m16n8k16.row.col.f32.bf16.bf16.f32 "
        "{%0,%1,%2,%3}, {%4,%5,%6,%7}, {%8,%9}, {%0,%1,%2,%3};"
        : "+f"(c0), "+f"(c1), "+f"(c2), "+f"(c3)
        : "r"(a0), "r"(a1), "r"(a2), "r"(a3), "r"(b0), "r"(b1));
}

/* ======================= edge dtype detect / decode ======================= */
__global__ void k_detect(const int* __restrict__ ei32) {
    int lane = threadIdx.x;
    int w = ei32[2 * lane + 1];
    unsigned any = __ballot_sync(0xFFFFFFFFu, w != 0);
    __shared__ int s_any;
    if (threadIdx.x == 0) s_any = 0;
    __syncthreads();
    if (any && (lane & 31) == 0) atomicOr(&s_any, 1);
    __syncthreads();
    if (threadIdx.x == 0) g_is64 = (s_any == 0) ? 1 : 0;
}
__device__ __forceinline__ int edge_decode(const int* ei32, int i, int& src, int& dst) {
    if (i >= N_EDGES) { src = dst = i - N_EDGES; return 1; }
    if (g_is64) { src = ei32[2 * i]; dst = ei32[2 * (N_EDGES + i)]; }
    else        { src = ei32[i];     dst = ei32[N_EDGES + i]; }
    return (src >= 0 && src < N_NODES && dst >= 0 && dst < N_NODES);
}

/* ============================ init / CSR ============================ */
__global__ void k_init(const float* __restrict__ b_lin) {
    int i = blockIdx.x * blockDim.x + threadIdx.x;
    if (i < N_NODES) { g_count[i] = 0; g_cursor[i] = 0; }
    if (i < LIN_OUT) g_bias2[i] = b_lin[i];
}
__global__ void k_hist(const int* __restrict__ ei32) {
    int i = blockIdx.x * blockDim.x + threadIdx.x;
    if (i >= E_TOT) return;
    int src, dst;
    if (edge_decode(ei32, i, src, dst)) atomicAdd(&g_count[dst], 1);
}
__global__ void k_scan() {
    __shared__ int s[1024];
    int tid = threadIdx.x;
    int carry = 0;
    for (int c = 0; c < 8; c++) {
        int idx = c * 1024 + tid;
        int v = (idx < N_NODES) ? g_count[idx] : 0;
        s[tid] = v;
        __syncthreads();
        for (int d = 1; d < 1024; d <<= 1) {
            int t = (tid >= d) ? s[tid - d] : 0;
            __syncthreads();
            s[tid] += t;
            __syncthreads();
        }
        if (idx <= N_NODES) g_off[idx] = carry + s[tid] - v;
        int tot = s[1023];
        __syncthreads();
        carry += tot;
    }
}
__global__ void k_scatter(const int* __restrict__ ei32) {
    int i = blockIdx.x * blockDim.x + threadIdx.x;
    if (i >= E_TOT) return;
    int src, dst;
    if (!edge_decode(ei32, i, src, dst)) return;
    int pos = g_off[dst] + atomicAdd(&g_cursor[dst], 1);
    g_csr_src[pos] = src;
}

/* =================== fp32 -> bf16 hi/lo split kernels =================== */
__global__ void k_split_x(const float* __restrict__ x) {
    int i = blockIdx.x * blockDim.x + threadIdx.x;
    if (i >= M_PAD * IN_C) return;
    float v = (i < N_NODES * IN_C) ? x[i] : 0.f;
    __nv_bfloat16 hi = __float2bfloat16(v);
    g_xhi[i] = hi;
    g_xlo[i] = __float2bfloat16(v - __bfloat162float(hi));
}
template <int WHICH>  /* 0: W_gat, 1: W_lin -- transpose + split */
__global__ void k_splitT(const float* __restrict__ in) {
    constexpr int K = WHICH ? HC : IN_C;
    constexpr int N = WHICH ? LIN_OUT : HC;
    __nv_bfloat16* ohi = WHICH ? g_wlin_hi : g_wgat_hi;
    __nv_bfloat16* olo = WHICH ? g_wlin_lo : g_wgat_lo;
    __shared__ float t[32][33];
    int tx = threadIdx.x, ty = threadIdx.y;
    int n0 = blockIdx.x * 32, k0 = blockIdx.y * 32;
#pragma unroll
    for (int r = 0; r < 4; r++)
        t[ty + 8 * r][tx] = in[(size_t)(k0 + ty + 8 * r) * N + n0 + tx];
    __syncthreads();
#pragma unroll
    for (int r = 0; r < 4; r++) {
        float v = t[tx][ty + 8 * r];
        __nv_bfloat16 hi = __float2bfloat16(v);
        size_t o = (size_t)(n0 + ty + 8 * r) * K + k0 + tx;
        ohi[o] = hi;
        olo[o] = __float2bfloat16(v - __bfloat162float(hi));
    }
}
__global__ void k_padagg() {
    int i = blockIdx.x * blockDim.x + threadIdx.x;
    if (i >= (M_PAD - N_NODES) * HC) return;
    __nv_bfloat16 z = __float2bfloat16(0.f);
    g_agghi[(size_t)N_NODES * HC + i] = z;
    g_agglo[(size_t)N_NODES * HC + i] = z;
}

/* ==================== HMMA GEMM (bf16 split-3, fp32 acc) ====================
 * C = A @ B^T. A [M_PAD,K] row-major bf16 (hi/lo), B [Ntot,K] row-major bf16
 * (pre-transposed weights). CTA tile 128x128, BK=32, cp.async double buffer,
 * 8 warps (2x4), each 64x32 via m16n8k16.
 * MODE 0: g_h = x @ W_gat^T           (Ktot=128,  Ntot=4096)
 * MODE 1: Cout = agg @ W_lin^T + bias (Ktot=4096, Ntot=512)  */
#define BK       32
#define SSTRIDE  40   /* bf16 elems per smem row (32 + 8 pad); 80 B */
template <int MODE>
__global__ __launch_bounds__(256)
void hmma_gemm(float* __restrict__ CoutParam) {
    constexpr int Ktot = MODE ? HC : IN_C;
    constexpr int Ntot = MODE ? LIN_OUT : HC;
    constexpr int KCP = Ktot / BK;         /* chunks per pass */
    constexpr int NKC = 3 * KCP;           /* total chunks (3 passes) */

    const __nv_bfloat16* Ap[3];
    const __nv_bfloat16* Bp[3];
    if (MODE == 0) {
        Ap[0] = g_xhi; Ap[1] = g_xhi; Ap[2] = g_xlo;
        Bp[0] = g_wgat_hi; Bp[1] = g_wgat_lo; Bp[2] = g_wgat_hi;
    } else {
        Ap[0] = g_agghi; Ap[1] = g_agghi; Ap[2] = g_agglo;
        Bp[0] = g_wlin_hi; Bp[1] = g_wlin_lo; Bp[2] = g_wlin_hi;
    }
    float* Cout = (MODE == 0) ? (float*)g_h : CoutParam;

    __shared__ __align__(16) __nv_bfloat16 sA[2][128 * SSTRIDE];
    __shared__ __align__(16) __nv_bfloat16 sB[2][128 * SSTRIDE];

    int tid = threadIdx.x, lane = tid & 31, wid = tid >> 5;
    int wm = wid >> 2, wn = wid & 3;          /* warp grid 2 x 4 */
    int m0 = blockIdx.y * 128, n0 = blockIdx.x * 128;

    /* cp.async: 512 16B-chunks per operand buffer, 2 per thread */
    int c0 = tid, c1 = tid + 256;
    int r0c = c0 >> 2, f0 = c0 & 3;
    int r1c = c1 >> 2, f1 = c1 & 3;
    uint32_t sA0[2], sA1[2], sB0[2], sB1[2];
#pragma unroll
    for (int b = 0; b < 2; b++) {
        sA0[b] = smem_u32(&sA[b][r0c * SSTRIDE + f0 * 8]);
        sA1[b] = smem_u32(&sA[b][r1c * SSTRIDE + f1 * 8]);
        sB0[b] = smem_u32(&sB[b][r0c * SSTRIDE + f0 * 8]);
        sB1[b] = smem_u32(&sB[b][r1c * SSTRIDE + f1 * 8]);
    }

    auto issue_load = [&](int cc, int b) {
        int pass = cc / KCP;
        size_t koff = (size_t)(cc % KCP) * BK;
        const __nv_bfloat16* A = Ap[pass];
        const __nv_bfloat16* B = Bp[pass];
        cp_async16(sA0[b], A + (size_t)(m0 + r0c) * Ktot + koff + f0 * 8);
        cp_async16(sA1[b], A + (size_t)(m0 + r1c) * Ktot + koff + f1 * 8);
        cp_async16(sB0[b], B + (size_t)(n0 + r0c) * Ktot + koff + f0 * 8);
        cp_async16(sB1[b], B + (size_t)(n0 + r1c) * Ktot + koff + f1 * 8);
        cp_commit();
    };

    float acc[4][4][4];
#pragma unroll
    for (int i = 0; i < 4; i++)
#pragma unroll
        for (int j = 0; j < 4; j++)
#pragma unroll
            for (int k = 0; k < 4; k++) acc[i][j][k] = 0.f;

    /* ldmatrix lane addressing (per-warp constant parts) */
    int a_row = (lane & 7) + ((lane >> 3) & 1) * 8;   /* within 16-row tile */
    int a_col = ((lane >> 4) & 1) * 8;                /* 0 or 8 */
    int b_row = (lane & 7) + ((lane >> 4) & 1) * 8;   /* within 16-n pair   */
    int b_col = ((lane >> 3) & 1) * 8;

    issue_load(0, 0);

    for (int cc = 0; cc < NKC; cc++) {
        int b = cc & 1;
        if (cc + 1 < NKC) issue_load(cc + 1, b ^ 1);
        if (cc + 1 < NKC) cp_wait<1>(); else cp_wait<0>();
        __syncthreads();

#pragma unroll
        for (int kk = 0; kk < 2; kk++) {
            uint32_t a[4][4], bb[4][2];
#pragma unroll
            for (int mt = 0; mt < 4; mt++) {
                uint32_t addr = smem_u32(&sA[b][(wm * 64 + mt * 16 + a_row) * SSTRIDE
                                               + kk * 16 + a_col]);
                ldm_x4(addr, a[mt][0], a[mt][1], a[mt][2], a[mt][3]);
            }
#pragma unroll
            for (int np = 0; np < 2; np++) {   /* pair of n-tiles per x4 */
                uint32_t addr = smem_u32(&sB[b][(wn * 32 + np * 16 + b_row) * SSTRIDE
                                               + kk * 16 + b_col]);
                uint32_t r0, r1, r2, r3;
                ldm_x4(addr, r0, r1, r2, r3);
                bb[np * 2][0] = r0; bb[np * 2][1] = r1;
                bb[np * 2 + 1][0] = r2; bb[np * 2 + 1][1] = r3;
            }
#pragma unroll
            for (int mt = 0; mt < 4; mt++)
#pragma unroll
                for (int nt = 0; nt < 4; nt++)
                    mma_bf16(acc[mt][nt][0], acc[mt][nt][1],
                             acc[mt][nt][2], acc[mt][nt][3],
                             a[mt][0], a[mt][1], a[mt][2], a[mt][3],
                             bb[nt][0], bb[nt][1]);
        }
        __syncthreads();
    }

    /* epilogue: c0,c1 -> (row, col..col+1); c2,c3 -> (row+8, ...) */
    int lrow = lane >> 2, lcol = (lane & 3) * 2;
#pragma unroll
    for (int mt = 0; mt < 4; mt++) {
        int r = m0 + wm * 64 + mt * 16 + lrow;
#pragma unroll
        for (int half = 0; half < 2; half++) {
            int rr = r + half * 8;
            if (rr < N_NODES) {
                float* cp = Cout + (size_t)rr * Ntot;
#pragma unroll
                for (int nt = 0; nt < 4; nt++) {
                    int cbase = n0 + wn * 32 + nt * 8 + lcol;
                    float v0 = acc[mt][nt][half * 2];
                    float v1 = acc[mt][nt][half * 2 + 1];
                    if (MODE == 1) { v0 += g_bias2[cbase]; v1 += g_bias2[cbase + 1]; }
                    cp[cbase] = v0;
                    cp[cbase + 1] = v1;
                }
            }
        }
    }
}

/* ---------------------- per-node attention logits ---------------------- */
__global__ void k_att(const float* __restrict__ att_src,
                      const float* __restrict__ att_dst) {
    int n = blockIdx.x;
    int w = threadIdx.x >> 5;
    int lane = threadIdx.x & 31;
    const float* hrow = g_h + (size_t)n * HC + w * OUT_C;
    const float* as = att_src + w * OUT_C;
    const float* ad = att_dst + w * OUT_C;
    float s = 0.f, d = 0.f;
    for (int c = lane; c < OUT_C; c += 32) {
        float hv = hrow[c];
        s += hv * as[c];
        d += hv * ad[c];
    }
#pragma unroll
    for (int o = 16; o; o >>= 1) {
        s += __shfl_xor_sync(0xFFFFFFFFu, s, o);
        d += __shfl_xor_sync(0xFFFFFFFFu, d, o);
    }
    if (lane == 0) {
        g_asrc[n * HEADS + w] = s;
        g_adst[n * HEADS + w] = d;
    }
}

/* ---------------------- edge softmax (one warp per dst) ---------------------- */
__global__ void k_softmax() {
    int gwarp = (blockIdx.x * blockDim.x + threadIdx.x) >> 5;
    int lane = threadIdx.x & 31;
    if (gwarp >= N_NODES) return;
    int beg = g_off[gwarp], end = g_off[gwarp + 1];
    for (int h = 0; h < HEADS; h++) {
        float ad = g_adst[gwarp * HEADS + h];
        float m = -1e30f;
        for (int e = beg + lane; e < end; e += 32) {
            float v = g_asrc[g_csr_src[e] * HEADS + h] + ad;
            v = v > 0.f ? v : NEG_SLOPE * v;
            m = fmaxf(m, v);
        }
#pragma unroll
        for (int o = 16; o; o >>= 1) m = fmaxf(m, __shfl_xor_sync(0xFFFFFFFFu, m, o));
        float s = 0.f;
        for (int e = beg + lane; e < end; e += 32) {
            float v = g_asrc[g_csr_src[e] * HEADS + h] + ad;
            v = v > 0.f ? v : NEG_SLOPE * v;
            s += expf(v - m);
        }
#pragma unroll
        for (int o = 16; o; o >>= 1) s += __shfl_xor_sync(0xFFFFFFFFu, s, o);
        float inv = 1.f / (s + EPS_F);
        for (int e = beg + lane; e < end; e += 32) {
            float v = g_asrc[g_csr_src[e] * HEADS + h] + ad;
            v = v > 0.f ? v : NEG_SLOPE * v;
            g_alpha[(size_t)e * HEADS + h] = expf(v - m) * inv;
        }
    }
}

/* -------- aggregation (gather per dst) -> bf16 hi/lo split output -------- */
__global__ __launch_bounds__(512) void k_agg() {
    int n = blockIdx.x;
    int t = threadIdx.x;
    float acc[HEADS];
#pragma unroll
    for (int j = 0; j < HEADS; j++) acc[j] = 0.f;
    int beg = g_off[n], end = g_off[n + 1];
    for (int s = beg; s < end; s++) {
        int src = g_csr_src[s];
        const float* hrow = g_h + (size_t)src * HC;
        const float* al = g_alpha + (size_t)s * HEADS;
#pragma unroll
        for (int j = 0; j < HEADS; j++)
            acc[j] += al[j] * hrow[j * OUT_C + t];
    }
#pragma unroll
    for (int j = 0; j < HEADS; j++) {
        float v = acc[j];
        __nv_bfloat16 hi = __float2bfloat16(v);
        size_t o = (size_t)n * HC + j * OUT_C + t;
        g_agghi[o] = hi;
        g_agglo[o] = __float2bfloat16(v - __bfloat162float(hi));
    }
}

/* ---------------------- fused bias2 = b_lin + b_gat @ W_lin ---------------------- */
__global__ void k_bias2(const float* __restrict__ b_gat,
                        const float* __restrict__ W_lin) {
    int t = threadIdx.x;
    int k0 = blockIdx.x * 128;
    float acc = 0.f;
    for (int k = k0; k < k0 + 128; k++)
        acc += b_gat[k] * W_lin[(size_t)k * LIN_OUT + t];
    atomicAdd(&g_bias2[t], acc);
}

/* ---------------------------- launch ---------------------------- */
extern "C" void kernel_launch(void* const* d_in, const int* in_sizes, int n_in,
                              void* d_out, int out_size) {
    const float* x       = (const float*)d_in[0];
    const int*   ei32    = (const int*)d_in[1];
    const float* W_gat   = (const float*)d_in[2];
    const float* b_gat   = (const float*)d_in[3];
    const float* att_src = (const float*)d_in[4];
    const float* att_dst = (const float*)d_in[5];
    const float* W_lin   = (const float*)d_in[6];
    const float* b_lin   = (const float*)d_in[7];
    float* out = (float*)d_out;

    k_detect<<<1, 64>>>(ei32);
    k_init<<<(N_NODES + 255) / 256, 256>>>(b_lin);
    k_hist<<<(E_TOT + 255) / 256, 256>>>(ei32);
    k_scan<<<1, 1024>>>();
    k_scatter<<<(E_TOT + 255) / 256, 256>>>(ei32);
    k_bias2<<<32, LIN_OUT>>>(b_gat, W_lin);

    k_split_x<<<(M_PAD * IN_C + 255) / 256, 256>>>(x);
    { dim3 g(HC / 32, IN_C / 32), b(32, 8); k_splitT<0><<<g, b>>>(W_gat); }
    { dim3 g(LIN_OUT / 32, HC / 32), b(32, 8); k_splitT<1><<<g, b>>>(W_lin); }
    k_padagg<<<((M_PAD - N_NODES) * HC + 255) / 256, 256>>>();

    /* GEMM1: g_h = x @ W_gat^T (HMMA split-3) */
    { dim3 grid(HC / 128, M_PAD / 128); hmma_gemm<0><<<grid, 256>>>(nullptr); }

    k_att<<<N_NODES, 256>>>(att_src, att_dst);
    k_softmax<<<(N_NODES * 32 + 255) / 256, 256>>>();
    k_agg<<<N_NODES, 512>>>();

    /* GEMM2: out = agg @ W_lin^T + bias2 (HMMA split-3) */
    { dim3 grid(LIN_OUT / 128, M_PAD / 128); hmma_gemm<1><<<grid, 256>>>(out); }
}

// round 8
// speedup vs baseline: 1.8993x; 1.0722x over previous
#include <cuda_runtime.h>
#include <cuda_bf16.h>
#include <math.h>
#include <stdint.h>

#define N_NODES 8000
#define M_PAD   8064                  /* 63 * 128 */
#define N_EDGES 64000
#define E_TOT   (N_EDGES + N_NODES)
#define HEADS   8
#define OUT_C   512
#define HC      (HEADS * OUT_C)       /* 4096 */
#define IN_C    128
#define LIN_OUT 512
#define NEG_SLOPE 0.2f
#define EPS_F   1e-16f

/* ------------- scratch (static device globals; no allocation) ------------- */
__device__ float g_h[(size_t)N_NODES * HC];
__device__ __nv_bfloat16 g_xhi[(size_t)M_PAD * IN_C];
__device__ __nv_bfloat16 g_xlo[(size_t)M_PAD * IN_C];
__device__ __nv_bfloat16 g_wgat_hi[(size_t)HC * IN_C];    /* W_gat^T [4096,128] */
__device__ __nv_bfloat16 g_wgat_lo[(size_t)HC * IN_C];
__device__ __nv_bfloat16 g_agghi[(size_t)M_PAD * HC];
__device__ __nv_bfloat16 g_agglo[(size_t)M_PAD * HC];
__device__ __nv_bfloat16 g_wlin_hi[(size_t)LIN_OUT * HC]; /* W_lin^T [512,4096] */
__device__ __nv_bfloat16 g_wlin_lo[(size_t)LIN_OUT * HC];
__device__ float g_asrc[N_NODES * HEADS];
__device__ float g_adst[N_NODES * HEADS];
__device__ int   g_count[N_NODES];
__device__ int   g_cursor[N_NODES];
__device__ int   g_off[N_NODES + 1];
__device__ int   g_csr_src[E_TOT];
__device__ float g_alpha[(size_t)E_TOT * HEADS];
__device__ float g_bias2[LIN_OUT];
__device__ int   g_is64;

/* ============================ PTX helpers (family-safe) ============================ */
__device__ __forceinline__ uint32_t smem_u32(const void* p) {
    uint32_t a;
    asm("{ .reg .u64 t; cvta.to.shared.u64 t, %1; cvt.u32.u64 %0, t; }"
        : "=r"(a) : "l"(p));
    return a;
}
__device__ __forceinline__ void cp_async16(uint32_t s, const void* g) {
    asm volatile("cp.async.cg.shared.global [%0], [%1], 16;" :: "r"(s), "l"(g));
}
__device__ __forceinline__ void cp_commit() {
    asm volatile("cp.async.commit_group;" ::: "memory");
}
template <int N>
__device__ __forceinline__ void cp_wait() {
    asm volatile("cp.async.wait_group %0;" :: "n"(N) : "memory");
}
__device__ __forceinline__ void ldm_x4(uint32_t addr, uint32_t& r0, uint32_t& r1,
                                       uint32_t& r2, uint32_t& r3) {
    asm volatile("ldmatrix.sync.aligned.m8n8.x4.shared.b16 {%0,%1,%2,%3}, [%4];"
                 : "=r"(r0), "=r"(r1), "=r"(r2), "=r"(r3) : "r"(addr));
}
__device__ __forceinline__ void mma_bf16(float& c0, float& c1, float& c2, float& c3,
                                         uint32_t a0, uint32_t a1, uint32_t a2, uint32_t a3,
                                         uint32_t b0, uint32_t b1) {
    asm volatile(
        "mma.sync.aligned.m16n8k16.row.col.f32.bf16.bf16.f32 "
        "{%0,%1,%2,%3}, {%4,%5,%6,%7}, {%8,%9}, {%0,%1,%2,%3};"
        : "+f"(c0), "+f"(c1), "+f"(c2), "+f"(c3)
        : "r"(a0), "r"(a1), "r"(a2), "r"(a3), "r"(b0), "r"(b1));
}

/* ======================= edge dtype detect / decode ======================= */
__global__ void k_detect(const int* __restrict__ ei32) {
    int lane = threadIdx.x;
    int w = ei32[2 * lane + 1];
    unsigned any = __ballot_sync(0xFFFFFFFFu, w != 0);
    __shared__ int s_any;
    if (threadIdx.x == 0) s_any = 0;
    __syncthreads();
    if (any && (lane & 31) == 0) atomicOr(&s_any, 1);
    __syncthreads();
    if (threadIdx.x == 0) g_is64 = (s_any == 0) ? 1 : 0;
}
__device__ __forceinline__ int edge_decode(const int* ei32, int i, int& src, int& dst) {
    if (i >= N_EDGES) { src = dst = i - N_EDGES; return 1; }
    if (g_is64) { src = ei32[2 * i]; dst = ei32[2 * (N_EDGES + i)]; }
    else        { src = ei32[i];     dst = ei32[N_EDGES + i]; }
    return (src >= 0 && src < N_NODES && dst >= 0 && dst < N_NODES);
}

/* ============================ init / CSR ============================ */
__global__ void k_init(const float* __restrict__ b_lin) {
    int i = blockIdx.x * blockDim.x + threadIdx.x;
    if (i < N_NODES) { g_count[i] = 0; g_cursor[i] = 0; }
    if (i < LIN_OUT) g_bias2[i] = b_lin[i];
}
__global__ void k_hist(const int* __restrict__ ei32) {
    int i = blockIdx.x * blockDim.x + threadIdx.x;
    if (i >= E_TOT) return;
    int src, dst;
    if (edge_decode(ei32, i, src, dst)) atomicAdd(&g_count[dst], 1);
}
__global__ void k_scan() {
    __shared__ int s[1024];
    int tid = threadIdx.x;
    int carry = 0;
    for (int c = 0; c < 8; c++) {
        int idx = c * 1024 + tid;
        int v = (idx < N_NODES) ? g_count[idx] : 0;
        s[tid] = v;
        __syncthreads();
        for (int d = 1; d < 1024; d <<= 1) {
            int t = (tid >= d) ? s[tid - d] : 0;
            __syncthreads();
            s[tid] += t;
            __syncthreads();
        }
        if (idx <= N_NODES) g_off[idx] = carry + s[tid] - v;
        int tot = s[1023];
        __syncthreads();
        carry += tot;
    }
}
__global__ void k_scatter(const int* __restrict__ ei32) {
    int i = blockIdx.x * blockDim.x + threadIdx.x;
    if (i >= E_TOT) return;
    int src, dst;
    if (!edge_decode(ei32, i, src, dst)) return;
    int pos = g_off[dst] + atomicAdd(&g_cursor[dst], 1);
    g_csr_src[pos] = src;
}

/* =================== fp32 -> bf16 hi/lo split kernels =================== */
__global__ void k_split_x(const float* __restrict__ x) {
    int i = blockIdx.x * blockDim.x + threadIdx.x;
    if (i >= M_PAD * IN_C) return;
    float v = (i < N_NODES * IN_C) ? x[i] : 0.f;
    __nv_bfloat16 hi = __float2bfloat16(v);
    g_xhi[i] = hi;
    g_xlo[i] = __float2bfloat16(v - __bfloat162float(hi));
}
template <int WHICH>  /* 0: W_gat, 1: W_lin -- transpose + split */
__global__ void k_splitT(const float* __restrict__ in) {
    constexpr int K = WHICH ? HC : IN_C;
    constexpr int N = WHICH ? LIN_OUT : HC;
    __nv_bfloat16* ohi = WHICH ? g_wlin_hi : g_wgat_hi;
    __nv_bfloat16* olo = WHICH ? g_wlin_lo : g_wgat_lo;
    __shared__ float t[32][33];
    int tx = threadIdx.x, ty = threadIdx.y;
    int n0 = blockIdx.x * 32, k0 = blockIdx.y * 32;
#pragma unroll
    for (int r = 0; r < 4; r++)
        t[ty + 8 * r][tx] = in[(size_t)(k0 + ty + 8 * r) * N + n0 + tx];
    __syncthreads();
#pragma unroll
    for (int r = 0; r < 4; r++) {
        float v = t[tx][ty + 8 * r];
        __nv_bfloat16 hi = __float2bfloat16(v);
        size_t o = (size_t)(n0 + ty + 8 * r) * K + k0 + tx;
        ohi[o] = hi;
        olo[o] = __float2bfloat16(v - __bfloat162float(hi));
    }
}
__global__ void k_padagg() {
    int i = blockIdx.x * blockDim.x + threadIdx.x;
    if (i >= (M_PAD - N_NODES) * HC) return;
    __nv_bfloat16 z = __float2bfloat16(0.f);
    g_agghi[(size_t)N_NODES * HC + i] = z;
    g_agglo[(size_t)N_NODES * HC + i] = z;
}

/* ============ HMMA GEMM, fused split-3 (single K-sweep, fp32 acc) ============
 * C = A @ B^T with A = Ahi + Alo, B = Bhi + Blo (bf16 pairs).
 * Per K-chunk (BK=32): load ALL FOUR tiles (Ahi,Alo,Bhi,Blo) once, issue the
 * three products hi*hi + hi*lo + lo*hi into the same fp32 accumulators.
 * 3-stage cp.async pipeline, dynamic smem = 3 * 40 KB = 120 KB.
 * MODE 0: g_h = x @ W_gat^T           (Ktot=128,  Ntot=4096)
 * MODE 1: Cout = agg @ W_lin^T + bias (Ktot=4096, Ntot=512)  */
#define BK       32
#define SSTRIDE  40                    /* bf16 per smem row: 32 + 8 pad (80 B) */
#define TILE_B   (128 * SSTRIDE * 2)   /* 10240 B per tile */
#define STAGE_B  (4 * TILE_B)          /* 40960 B per stage */
#define NSTAGE   3
template <int MODE>
__global__ __launch_bounds__(256)
void hmma_gemm(float* __restrict__ CoutParam) {
    constexpr int Ktot = MODE ? HC : IN_C;
    constexpr int Ntot = MODE ? LIN_OUT : HC;
    constexpr int KCP = Ktot / BK;

    const __nv_bfloat16 *Ah, *Al, *Bh, *Bl;
    if (MODE == 0) { Ah = g_xhi;  Al = g_xlo;  Bh = g_wgat_hi; Bl = g_wgat_lo; }
    else           { Ah = g_agghi; Al = g_agglo; Bh = g_wlin_hi; Bl = g_wlin_lo; }
    float* Cout = (MODE == 0) ? (float*)g_h : CoutParam;

    extern __shared__ __align__(16) uint8_t dsm[];

    int tid = threadIdx.x, lane = tid & 31, wid = tid >> 5;
    int wm = wid >> 2, wn = wid & 3;          /* warp grid 2 x 4 */
    int m0 = blockIdx.y * 128, n0 = blockIdx.x * 128;

    /* load mapping: thread covers rows r0c and r0c+64, 16B quarter f */
    int r0c = tid >> 2, f = tid & 3;
    uint32_t dst_off0 = (uint32_t)(r0c * (SSTRIDE * 2) + f * 16);
    uint32_t dst_off1 = dst_off0 + 64 * (SSTRIDE * 2);

    auto issue_load = [&](int cc, int st) {
        size_t koff = (size_t)cc * BK + f * 8;
        uint8_t* base = dsm + st * STAGE_B;
        uint32_t s0 = smem_u32(base);
        /* Ahi, Alo tiles (rows from m0), Bhi, Blo tiles (rows from n0) */
        cp_async16(s0 + 0 * TILE_B + dst_off0, Ah + (size_t)(m0 + r0c) * Ktot + koff);
        cp_async16(s0 + 0 * TILE_B + dst_off1, Ah + (size_t)(m0 + r0c + 64) * Ktot + koff);
        cp_async16(s0 + 1 * TILE_B + dst_off0, Al + (size_t)(m0 + r0c) * Ktot + koff);
        cp_async16(s0 + 1 * TILE_B + dst_off1, Al + (size_t)(m0 + r0c + 64) * Ktot + koff);
        cp_async16(s0 + 2 * TILE_B + dst_off0, Bh + (size_t)(n0 + r0c) * Ktot + koff);
        cp_async16(s0 + 2 * TILE_B + dst_off1, Bh + (size_t)(n0 + r0c + 64) * Ktot + koff);
        cp_async16(s0 + 3 * TILE_B + dst_off0, Bl + (size_t)(n0 + r0c) * Ktot + koff);
        cp_async16(s0 + 3 * TILE_B + dst_off1, Bl + (size_t)(n0 + r0c + 64) * Ktot + koff);
        cp_commit();
    };

    float acc[4][4][4];
#pragma unroll
    for (int i = 0; i < 4; i++)
#pragma unroll
        for (int j = 0; j < 4; j++)
#pragma unroll
            for (int k = 0; k < 4; k++) acc[i][j][k] = 0.f;

    /* ldmatrix lane addressing (identical to R7-passing kernel) */
    int a_row = (lane & 7) + ((lane >> 3) & 1) * 8;
    int a_col = ((lane >> 4) & 1) * 8;
    int b_row = (lane & 7) + ((lane >> 4) & 1) * 8;
    int b_col = ((lane >> 3) & 1) * 8;

    issue_load(0, 0);
    if (KCP > 1) issue_load(1, 1);

    for (int cc = 0; cc < KCP; cc++) {
        int st = cc % NSTAGE;
        if (cc + 2 < KCP) { issue_load(cc + 2, (cc + 2) % NSTAGE); cp_wait<2>(); }
        else if (cc + 1 < KCP) cp_wait<1>();
        else cp_wait<0>();
        __syncthreads();

        const __nv_bfloat16* sAh = (const __nv_bfloat16*)(dsm + st * STAGE_B + 0 * TILE_B);
        const __nv_bfloat16* sAl = (const __nv_bfloat16*)(dsm + st * STAGE_B + 1 * TILE_B);
        const __nv_bfloat16* sBh = (const __nv_bfloat16*)(dsm + st * STAGE_B + 2 * TILE_B);
        const __nv_bfloat16* sBl = (const __nv_bfloat16*)(dsm + st * STAGE_B + 3 * TILE_B);

#pragma unroll
        for (int kk = 0; kk < 2; kk++) {
            uint32_t ah[4][4], al[4][4], bh[4][2], bl[4][2];
#pragma unroll
            for (int mt = 0; mt < 4; mt++) {
                int roff = (wm * 64 + mt * 16 + a_row) * SSTRIDE + kk * 16 + a_col;
                ldm_x4(smem_u32(sAh + roff), ah[mt][0], ah[mt][1], ah[mt][2], ah[mt][3]);
                ldm_x4(smem_u32(sAl + roff), al[mt][0], al[mt][1], al[mt][2], al[mt][3]);
            }
#pragma unroll
            for (int np = 0; np < 2; np++) {
                int roff = (wn * 32 + np * 16 + b_row) * SSTRIDE + kk * 16 + b_col;
                uint32_t r0, r1, r2, r3;
                ldm_x4(smem_u32(sBh + roff), r0, r1, r2, r3);
                bh[np * 2][0] = r0; bh[np * 2][1] = r1;
                bh[np * 2 + 1][0] = r2; bh[np * 2 + 1][1] = r3;
                ldm_x4(smem_u32(sBl + roff), r0, r1, r2, r3);
                bl[np * 2][0] = r0; bl[np * 2][1] = r1;
                bl[np * 2 + 1][0] = r2; bl[np * 2 + 1][1] = r3;
            }
#pragma unroll
            for (int mt = 0; mt < 4; mt++)
#pragma unroll
                for (int nt = 0; nt < 4; nt++) {
                    mma_bf16(acc[mt][nt][0], acc[mt][nt][1], acc[mt][nt][2], acc[mt][nt][3],
                             ah[mt][0], ah[mt][1], ah[mt][2], ah[mt][3],
                             bh[nt][0], bh[nt][1]);
                    mma_bf16(acc[mt][nt][0], acc[mt][nt][1], acc[mt][nt][2], acc[mt][nt][3],
                             ah[mt][0], ah[mt][1], ah[mt][2], ah[mt][3],
                             bl[nt][0], bl[nt][1]);
                    mma_bf16(acc[mt][nt][0], acc[mt][nt][1], acc[mt][nt][2], acc[mt][nt][3],
                             al[mt][0], al[mt][1], al[mt][2], al[mt][3],
                             bh[nt][0], bh[nt][1]);
                }
        }
        __syncthreads();
    }

    /* epilogue */
    int lrow = lane >> 2, lcol = (lane & 3) * 2;
#pragma unroll
    for (int mt = 0; mt < 4; mt++) {
        int r = m0 + wm * 64 + mt * 16 + lrow;
#pragma unroll
        for (int half = 0; half < 2; half++) {
            int rr = r + half * 8;
            if (rr < N_NODES) {
                float* cp = Cout + (size_t)rr * Ntot;
#pragma unroll
                for (int nt = 0; nt < 4; nt++) {
                    int cbase = n0 + wn * 32 + nt * 8 + lcol;
                    float v0 = acc[mt][nt][half * 2];
                    float v1 = acc[mt][nt][half * 2 + 1];
                    if (MODE == 1) { v0 += g_bias2[cbase]; v1 += g_bias2[cbase + 1]; }
                    cp[cbase] = v0;
                    cp[cbase + 1] = v1;
                }
            }
        }
    }
}

/* ---------------------- per-node attention logits ---------------------- */
__global__ void k_att(const float* __restrict__ att_src,
                      const float* __restrict__ att_dst) {
    int n = blockIdx.x;
    int w = threadIdx.x >> 5;
    int lane = threadIdx.x & 31;
    const float* hrow = g_h + (size_t)n * HC + w * OUT_C;
    const float* as = att_src + w * OUT_C;
    const float* ad = att_dst + w * OUT_C;
    float s = 0.f, d = 0.f;
    for (int c = lane; c < OUT_C; c += 32) {
        float hv = hrow[c];
        s += hv * as[c];
        d += hv * ad[c];
    }
#pragma unroll
    for (int o = 16; o; o >>= 1) {
        s += __shfl_xor_sync(0xFFFFFFFFu, s, o);
        d += __shfl_xor_sync(0xFFFFFFFFu, d, o);
    }
    if (lane == 0) {
        g_asrc[n * HEADS + w] = s;
        g_adst[n * HEADS + w] = d;
    }
}

/* ---------------------- edge softmax (one warp per dst) ---------------------- */
__global__ void k_softmax() {
    int gwarp = (blockIdx.x * blockDim.x + threadIdx.x) >> 5;
    int lane = threadIdx.x & 31;
    if (gwarp >= N_NODES) return;
    int beg = g_off[gwarp], end = g_off[gwarp + 1];
    for (int h = 0; h < HEADS; h++) {
        float ad = g_adst[gwarp * HEADS + h];
        float m = -1e30f;
        for (int e = beg + lane; e < end; e += 32) {
            float v = g_asrc[g_csr_src[e] * HEADS + h] + ad;
            v = v > 0.f ? v : NEG_SLOPE * v;
            m = fmaxf(m, v);
        }
#pragma unroll
        for (int o = 16; o; o >>= 1) m = fmaxf(m, __shfl_xor_sync(0xFFFFFFFFu, m, o));
        float s = 0.f;
        for (int e = beg + lane; e < end; e += 32) {
            float v = g_asrc[g_csr_src[e] * HEADS + h] + ad;
            v = v > 0.f ? v : NEG_SLOPE * v;
            s += expf(v - m);
        }
#pragma unroll
        for (int o = 16; o; o >>= 1) s += __shfl_xor_sync(0xFFFFFFFFu, s, o);
        float inv = 1.f / (s + EPS_F);
        for (int e = beg + lane; e < end; e += 32) {
            float v = g_asrc[g_csr_src[e] * HEADS + h] + ad;
            v = v > 0.f ? v : NEG_SLOPE * v;
            g_alpha[(size_t)e * HEADS + h] = expf(v - m) * inv;
        }
    }
}

/* -------- aggregation (gather per dst) -> bf16 hi/lo split output -------- */
__global__ __launch_bounds__(512) void k_agg() {
    int n = blockIdx.x;
    int t = threadIdx.x;
    float acc[HEADS];
#pragma unroll
    for (int j = 0; j < HEADS; j++) acc[j] = 0.f;
    int beg = g_off[n], end = g_off[n + 1];
    for (int s = beg; s < end; s++) {
        int src = g_csr_src[s];
        const float* hrow = g_h + (size_t)src * HC;
        const float* al = g_alpha + (size_t)s * HEADS;
#pragma unroll
        for (int j = 0; j < HEADS; j++)
            acc[j] += al[j] * hrow[j * OUT_C + t];
    }
#pragma unroll
    for (int j = 0; j < HEADS; j++) {
        float v = acc[j];
        __nv_bfloat16 hi = __float2bfloat16(v);
        size_t o = (size_t)n * HC + j * OUT_C + t;
        g_agghi[o] = hi;
        g_agglo[o] = __float2bfloat16(v - __bfloat162float(hi));
    }
}

/* ---------------------- fused bias2 = b_lin + b_gat @ W_lin ---------------------- */
__global__ void k_bias2(const float* __restrict__ b_gat,
                        const float* __restrict__ W_lin) {
    int t = threadIdx.x;
    int k0 = blockIdx.x * 128;
    float acc = 0.f;
    for (int k = k0; k < k0 + 128; k++)
        acc += b_gat[k] * W_lin[(size_t)k * LIN_OUT + t];
    atomicAdd(&g_bias2[t], acc);
}

/* ---------------------------- launch ---------------------------- */
extern "C" void kernel_launch(void* const* d_in, const int* in_sizes, int n_in,
                              void* d_out, int out_size) {
    const float* x       = (const float*)d_in[0];
    const int*   ei32    = (const int*)d_in[1];
    const float* W_gat   = (const float*)d_in[2];
    const float* b_gat   = (const float*)d_in[3];
    const float* att_src = (const float*)d_in[4];
    const float* att_dst = (const float*)d_in[5];
    const float* W_lin   = (const float*)d_in[6];
    const float* b_lin   = (const float*)d_in[7];
    float* out = (float*)d_out;

    /* 120 KB dynamic smem opt-in (idempotent; not a stream op) */
    cudaFuncSetAttribute(hmma_gemm<0>, cudaFuncAttributeMaxDynamicSharedMemorySize,
                         NSTAGE * STAGE_B);
    cudaFuncSetAttribute(hmma_gemm<1>, cudaFuncAttributeMaxDynamicSharedMemorySize,
                         NSTAGE * STAGE_B);

    /* order chosen so hmma_gemm<0> is launch idx 3 (profiler capture slot) */
    k_detect<<<1, 64>>>(ei32);
    k_split_x<<<(M_PAD * IN_C + 255) / 256, 256>>>(x);
    { dim3 g(HC / 32, IN_C / 32), b(32, 8); k_splitT<0><<<g, b>>>(W_gat); }
    { dim3 grid(HC / 128, M_PAD / 128);
      hmma_gemm<0><<<grid, 256, NSTAGE * STAGE_B>>>(nullptr); }

    k_init<<<(N_NODES + 255) / 256, 256>>>(b_lin);
    k_hist<<<(E_TOT + 255) / 256, 256>>>(ei32);
    k_scan<<<1, 1024>>>();
    k_scatter<<<(E_TOT + 255) / 256, 256>>>(ei32);
    k_bias2<<<32, LIN_OUT>>>(b_gat, W_lin);
    { dim3 g(LIN_OUT / 32, HC / 32), b(32, 8); k_splitT<1><<<g, b>>>(W_lin); }
    k_padagg<<<((M_PAD - N_NODES) * HC + 255) / 256, 256>>>();

    k_att<<<N_NODES, 256>>>(att_src, att_dst);
    k_softmax<<<(N_NODES * 32 + 255) / 256, 256>>>();
    k_agg<<<N_NODES, 512>>>();

    /* GEMM2: out = agg @ W_lin^T + bias2 */
    { dim3 grid(LIN_OUT / 128, M_PAD / 128);
      hmma_gemm<1><<<grid, 256, NSTAGE * STAGE_B>>>(out); }
}

// round 11
// speedup vs baseline: 2.1045x; 1.1080x over previous
#include <cuda_runtime.h>
#include <cuda_bf16.h>
#include <math.h>
#include <stdint.h>

#define N_NODES 8000
#define M_PAD   8064                  /* 63 * 128 */
#define N_EDGES 64000
#define E_TOT   (N_EDGES + N_NODES)
#define HEADS   8
#define OUT_C   512
#define HC      (HEADS * OUT_C)       /* 4096 */
#define IN_C    128
#define LIN_OUT 512
#define NEG_SLOPE 0.2f
#define EPS_F   1e-16f

/* ------------- scratch (static device globals; no allocation) ------------- */
__device__ float g_h[(size_t)N_NODES * HC];
__device__ __nv_bfloat16 g_xhi[(size_t)M_PAD * IN_C];
__device__ __nv_bfloat16 g_xlo[(size_t)M_PAD * IN_C];
__device__ __nv_bfloat16 g_wgat_hi[(size_t)HC * IN_C];    /* W_gat^T [4096,128] */
__device__ __nv_bfloat16 g_wgat_lo[(size_t)HC * IN_C];
__device__ __nv_bfloat16 g_agghi[(size_t)M_PAD * HC];
__device__ __nv_bfloat16 g_agglo[(size_t)M_PAD * HC];
__device__ __nv_bfloat16 g_wlin_hi[(size_t)LIN_OUT * HC]; /* W_lin^T [512,4096] */
__device__ __nv_bfloat16 g_wlin_lo[(size_t)LIN_OUT * HC];
__device__ float g_asrc[N_NODES * HEADS];
__device__ float g_adst[N_NODES * HEADS];
__device__ int   g_count[N_NODES];
__device__ int   g_cursor[N_NODES];
__device__ int   g_off[N_NODES + 1];
__device__ int   g_csr_src[E_TOT];
__device__ float g_alpha[(size_t)E_TOT * HEADS];
__device__ float g_bias2[LIN_OUT];
__device__ int   g_is64;

/* ============================ PTX helpers (family-safe) ============================ */
__device__ __forceinline__ uint32_t smem_u32(const void* p) {
    uint32_t a;
    asm("{ .reg .u64 t; cvta.to.shared.u64 t, %1; cvt.u32.u64 %0, t; }"
        : "=r"(a) : "l"(p));
    return a;
}
__device__ __forceinline__ void cp_async16(uint32_t s, const void* g) {
    asm volatile("cp.async.cg.shared.global [%0], [%1], 16;" :: "r"(s), "l"(g));
}
__device__ __forceinline__ void cp_commit() {
    asm volatile("cp.async.commit_group;" ::: "memory");
}
template <int N>
__device__ __forceinline__ void cp_wait() {
    asm volatile("cp.async.wait_group %0;" :: "n"(N) : "memory");
}
__device__ __forceinline__ void ldm_x4(uint32_t addr, uint32_t& r0, uint32_t& r1,
                                       uint32_t& r2, uint32_t& r3) {
    asm volatile("ldmatrix.sync.aligned.m8n8.x4.shared.b16 {%0,%1,%2,%3}, [%4];"
                 : "=r"(r0), "=r"(r1), "=r"(r2), "=r"(r3) : "r"(addr));
}
__device__ __forceinline__ void mma_bf16(float& c0, float& c1, float& c2, float& c3,
                                         uint32_t a0, uint32_t a1, uint32_t a2, uint32_t a3,
                                         uint32_t b0, uint32_t b1) {
    asm volatile(
        "mma.sync.aligned.m16n8k16.row.col.f32.bf16.bf16.f32 "
        "{%0,%1,%2,%3}, {%4,%5,%6,%7}, {%8,%9}, {%0,%1,%2,%3};"
        : "+f"(c0), "+f"(c1), "+f"(c2), "+f"(c3)
        : "r"(a0), "r"(a1), "r"(a2), "r"(a3), "r"(b0), "r"(b1));
}

/* ======================= edge dtype detect / decode ======================= */
__global__ void k_detect(const int* __restrict__ ei32) {
    int lane = threadIdx.x;
    int w = ei32[2 * lane + 1];
    unsigned any = __ballot_sync(0xFFFFFFFFu, w != 0);
    __shared__ int s_any;
    if (threadIdx.x == 0) s_any = 0;
    __syncthreads();
    if (any && (lane & 31) == 0) atomicOr(&s_any, 1);
    __syncthreads();
    if (threadIdx.x == 0) g_is64 = (s_any == 0) ? 1 : 0;
}
__device__ __forceinline__ int edge_decode(const int* ei32, int i, int& src, int& dst) {
    if (i >= N_EDGES) { src = dst = i - N_EDGES; return 1; }
    if (g_is64) { src = ei32[2 * i]; dst = ei32[2 * (N_EDGES + i)]; }
    else        { src = ei32[i];     dst = ei32[N_EDGES + i]; }
    return (src >= 0 && src < N_NODES && dst >= 0 && dst < N_NODES);
}

/* ============================ init / CSR ============================ */
__global__ void k_init(const float* __restrict__ b_lin) {
    int i = blockIdx.x * blockDim.x + threadIdx.x;
    if (i < N_NODES) { g_count[i] = 0; g_cursor[i] = 0; }
    if (i < LIN_OUT) g_bias2[i] = b_lin[i];
}
__global__ void k_hist(const int* __restrict__ ei32) {
    int i = blockIdx.x * blockDim.x + threadIdx.x;
    if (i >= E_TOT) return;
    int src, dst;
    if (edge_decode(ei32, i, src, dst)) atomicAdd(&g_count[dst], 1);
}
__global__ void k_scan() {
    __shared__ int s[1024];
    int tid = threadIdx.x;
    int carry = 0;
    for (int c = 0; c < 8; c++) {
        int idx = c * 1024 + tid;
        int v = (idx < N_NODES) ? g_count[idx] : 0;
        s[tid] = v;
        __syncthreads();
        for (int d = 1; d < 1024; d <<= 1) {
            int t = (tid >= d) ? s[tid - d] : 0;
            __syncthreads();
            s[tid] += t;
            __syncthreads();
        }
        if (idx <= N_NODES) g_off[idx] = carry + s[tid] - v;
        int tot = s[1023];
        __syncthreads();
        carry += tot;
    }
}
__global__ void k_scatter(const int* __restrict__ ei32) {
    int i = blockIdx.x * blockDim.x + threadIdx.x;
    if (i >= E_TOT) return;
    int src, dst;
    if (!edge_decode(ei32, i, src, dst)) return;
    int pos = g_off[dst] + atomicAdd(&g_cursor[dst], 1);
    g_csr_src[pos] = src;
}

/* =================== fp32 -> bf16 hi/lo split kernels =================== */
__global__ void k_split_x(const float* __restrict__ x) {
    int i = blockIdx.x * blockDim.x + threadIdx.x;
    if (i >= M_PAD * IN_C) return;
    float v = (i < N_NODES * IN_C) ? x[i] : 0.f;
    __nv_bfloat16 hi = __float2bfloat16(v);
    g_xhi[i] = hi;
    g_xlo[i] = __float2bfloat16(v - __bfloat162float(hi));
}
template <int WHICH>  /* 0: W_gat, 1: W_lin -- transpose + split */
__global__ void k_splitT(const float* __restrict__ in) {
    constexpr int K = WHICH ? HC : IN_C;
    constexpr int N = WHICH ? LIN_OUT : HC;
    __nv_bfloat16* ohi = WHICH ? g_wlin_hi : g_wgat_hi;
    __nv_bfloat16* olo = WHICH ? g_wlin_lo : g_wgat_lo;
    __shared__ float t[32][33];
    int tx = threadIdx.x, ty = threadIdx.y;
    int n0 = blockIdx.x * 32, k0 = blockIdx.y * 32;
#pragma unroll
    for (int r = 0; r < 4; r++)
        t[ty + 8 * r][tx] = in[(size_t)(k0 + ty + 8 * r) * N + n0 + tx];
    __syncthreads();
#pragma unroll
    for (int r = 0; r < 4; r++) {
        float v = t[tx][ty + 8 * r];
        __nv_bfloat16 hi = __float2bfloat16(v);
        size_t o = (size_t)(n0 + ty + 8 * r) * K + k0 + tx;
        ohi[o] = hi;
        olo[o] = __float2bfloat16(v - __bfloat162float(hi));
    }
}
__global__ void k_padagg() {
    int i = blockIdx.x * blockDim.x + threadIdx.x;
    if (i >= (M_PAD - N_NODES) * HC) return;
    __nv_bfloat16 z = __float2bfloat16(0.f);
    g_agghi[(size_t)N_NODES * HC + i] = z;
    g_agglo[(size_t)N_NODES * HC + i] = z;
}

/* ============ HMMA GEMM, fused split-3 (single K-sweep, fp32 acc) ============
 * Per K-chunk (BK=32): load all four tiles (Ahi,Alo,Bhi,Blo) once, issue
 * hi*hi + hi*lo + lo*hi into the same fp32 accumulators.
 * 2-stage cp.async pipeline, dynamic smem = 2 * 40 KB = 80 KB -> 2 CTAs/SM
 * (R8 profile: 1 CTA/SM, occ 12.4%, tensor 34.8% -> latency-bound; this
 *  doubles the resident warp pool).
 * MODE 0: g_h = x @ W_gat^T           (Ktot=128,  Ntot=4096)
 * MODE 1: Cout = agg @ W_lin^T + bias (Ktot=4096, Ntot=512)  */
#define BK       32
#define SSTRIDE  40                    /* bf16 per smem row: 32 + 8 pad (80 B) */
#define TILE_B   (128 * SSTRIDE * 2)   /* 10240 B per tile */
#define STAGE_B  (4 * TILE_B)          /* 40960 B per stage */
#define NSTAGE   2
template <int MODE>
__global__ __launch_bounds__(256, 2)
void hmma_gemm(float* __restrict__ CoutParam) {
    constexpr int Ktot = MODE ? HC : IN_C;
    constexpr int Ntot = MODE ? LIN_OUT : HC;
    constexpr int KCP = Ktot / BK;

    const __nv_bfloat16 *Ah, *Al, *Bh, *Bl;
    if (MODE == 0) { Ah = g_xhi;  Al = g_xlo;  Bh = g_wgat_hi; Bl = g_wgat_lo; }
    else           { Ah = g_agghi; Al = g_agglo; Bh = g_wlin_hi; Bl = g_wlin_lo; }
    float* Cout = (MODE == 0) ? (float*)g_h : CoutParam;

    extern __shared__ __align__(16) uint8_t dsm[];

    int tid = threadIdx.x, lane = tid & 31, wid = tid >> 5;
    int wm = wid >> 2, wn = wid & 3;          /* warp grid 2 x 4 */
    int m0 = blockIdx.y * 128, n0 = blockIdx.x * 128;

    /* load mapping: thread covers rows r0c and r0c+64, 16B quarter f */
    int r0c = tid >> 2, f = tid & 3;
    uint32_t dst_off0 = (uint32_t)(r0c * (SSTRIDE * 2) + f * 16);
    uint32_t dst_off1 = dst_off0 + 64 * (SSTRIDE * 2);

    auto issue_load = [&](int cc, int st) {
        size_t koff = (size_t)cc * BK + f * 8;
        uint8_t* base = dsm + st * STAGE_B;
        uint32_t s0 = smem_u32(base);
        cp_async16(s0 + 0 * TILE_B + dst_off0, Ah + (size_t)(m0 + r0c) * Ktot + koff);
        cp_async16(s0 + 0 * TILE_B + dst_off1, Ah + (size_t)(m0 + r0c + 64) * Ktot + koff);
        cp_async16(s0 + 1 * TILE_B + dst_off0, Al + (size_t)(m0 + r0c) * Ktot + koff);
        cp_async16(s0 + 1 * TILE_B + dst_off1, Al + (size_t)(m0 + r0c + 64) * Ktot + koff);
        cp_async16(s0 + 2 * TILE_B + dst_off0, Bh + (size_t)(n0 + r0c) * Ktot + koff);
        cp_async16(s0 + 2 * TILE_B + dst_off1, Bh + (size_t)(n0 + r0c + 64) * Ktot + koff);
        cp_async16(s0 + 3 * TILE_B + dst_off0, Bl + (size_t)(n0 + r0c) * Ktot + koff);
        cp_async16(s0 + 3 * TILE_B + dst_off1, Bl + (size_t)(n0 + r0c + 64) * Ktot + koff);
        cp_commit();
    };

    float acc[4][4][4];
#pragma unroll
    for (int i = 0; i < 4; i++)
#pragma unroll
        for (int j = 0; j < 4; j++)
#pragma unroll
            for (int k = 0; k < 4; k++) acc[i][j][k] = 0.f;

    int a_row = (lane & 7) + ((lane >> 3) & 1) * 8;
    int a_col = ((lane >> 4) & 1) * 8;
    int b_row = (lane & 7) + ((lane >> 4) & 1) * 8;
    int b_col = ((lane >> 3) & 1) * 8;

    issue_load(0, 0);
    if (KCP > 1) issue_load(1, 1);

    for (int cc = 0; cc < KCP; cc++) {
        int st = cc & 1;
        if (cc + 1 < KCP) cp_wait<1>(); else cp_wait<0>();
        __syncthreads();

        const __nv_bfloat16* sAh = (const __nv_bfloat16*)(dsm + st * STAGE_B + 0 * TILE_B);
        const __nv_bfloat16* sAl = (const __nv_bfloat16*)(dsm + st * STAGE_B + 1 * TILE_B);
        const __nv_bfloat16* sBh = (const __nv_bfloat16*)(dsm + st * STAGE_B + 2 * TILE_B);
        const __nv_bfloat16* sBl = (const __nv_bfloat16*)(dsm + st * STAGE_B + 3 * TILE_B);

#pragma unroll
        for (int kk = 0; kk < 2; kk++) {
            uint32_t ah[4][4], al[4][4], bh[4][2], bl[4][2];
#pragma unroll
            for (int mt = 0; mt < 4; mt++) {
                int roff = (wm * 64 + mt * 16 + a_row) * SSTRIDE + kk * 16 + a_col;
                ldm_x4(smem_u32(sAh + roff), ah[mt][0], ah[mt][1], ah[mt][2], ah[mt][3]);
                ldm_x4(smem_u32(sAl + roff), al[mt][0], al[mt][1], al[mt][2], al[mt][3]);
            }
#pragma unroll
            for (int np = 0; np < 2; np++) {
                int roff = (wn * 32 + np * 16 + b_row) * SSTRIDE + kk * 16 + b_col;
                uint32_t r0, r1, r2, r3;
                ldm_x4(smem_u32(sBh + roff), r0, r1, r2, r3);
                bh[np * 2][0] = r0; bh[np * 2][1] = r1;
                bh[np * 2 + 1][0] = r2; bh[np * 2 + 1][1] = r3;
                ldm_x4(smem_u32(sBl + roff), r0, r1, r2, r3);
                bl[np * 2][0] = r0; bl[np * 2][1] = r1;
                bl[np * 2 + 1][0] = r2; bl[np * 2 + 1][1] = r3;
            }
#pragma unroll
            for (int mt = 0; mt < 4; mt++)
#pragma unroll
                for (int nt = 0; nt < 4; nt++) {
                    mma_bf16(acc[mt][nt][0], acc[mt][nt][1], acc[mt][nt][2], acc[mt][nt][3],
                             ah[mt][0], ah[mt][1], ah[mt][2], ah[mt][3],
                             bh[nt][0], bh[nt][1]);
                    mma_bf16(acc[mt][nt][0], acc[mt][nt][1], acc[mt][nt][2], acc[mt][nt][3],
                             ah[mt][0], ah[mt][1], ah[mt][2], ah[mt][3],
                             bl[nt][0], bl[nt][1]);
                    mma_bf16(acc[mt][nt][0], acc[mt][nt][1], acc[mt][nt][2], acc[mt][nt][3],
                             al[mt][0], al[mt][1], al[mt][2], al[mt][3],
                             bh[nt][0], bh[nt][1]);
                }
        }
        __syncthreads();
        /* refill the stage just freed (2-stage: issue after compute) */
        if (cc + 2 < KCP) issue_load(cc + 2, st);
    }

    /* epilogue */
    int lrow = lane >> 2, lcol = (lane & 3) * 2;
#pragma unroll
    for (int mt = 0; mt < 4; mt++) {
        int r = m0 + wm * 64 + mt * 16 + lrow;
#pragma unroll
        for (int half = 0; half < 2; half++) {
            int rr = r + half * 8;
            if (rr < N_NODES) {
                float* cp = Cout + (size_t)rr * Ntot;
#pragma unroll
                for (int nt = 0; nt < 4; nt++) {
                    int cbase = n0 + wn * 32 + nt * 8 + lcol;
                    float v0 = acc[mt][nt][half * 2];
                    float v1 = acc[mt][nt][half * 2 + 1];
                    if (MODE == 1) { v0 += g_bias2[cbase]; v1 += g_bias2[cbase + 1]; }
                    cp[cbase] = v0;
                    cp[cbase + 1] = v1;
                }
            }
        }
    }
}

/* ---------------------- per-node attention logits ---------------------- */
__global__ void k_att(const float* __restrict__ att_src,
                      const float* __restrict__ att_dst) {
    int n = blockIdx.x;
    int w = threadIdx.x >> 5;
    int lane = threadIdx.x & 31;
    const float* hrow = g_h + (size_t)n * HC + w * OUT_C;
    const float* as = att_src + w * OUT_C;
    const float* ad = att_dst + w * OUT_C;
    float s = 0.f, d = 0.f;
    for (int c = lane; c < OUT_C; c += 32) {
        float hv = hrow[c];
        s += hv * as[c];
        d += hv * ad[c];
    }
#pragma unroll
    for (int o = 16; o; o >>= 1) {
        s += __shfl_xor_sync(0xFFFFFFFFu, s, o);
        d += __shfl_xor_sync(0xFFFFFFFFu, d, o);
    }
    if (lane == 0) {
        g_asrc[n * HEADS + w] = s;
        g_adst[n * HEADS + w] = d;
    }
}

/* ---------------------- edge softmax (one warp per dst) ---------------------- */
__global__ void k_softmax() {
    int gwarp = (blockIdx.x * blockDim.x + threadIdx.x) >> 5;
    int lane = threadIdx.x & 31;
    if (gwarp >= N_NODES) return;
    int beg = g_off[gwarp], end = g_off[gwarp + 1];
    for (int h = 0; h < HEADS; h++) {
        float ad = g_adst[gwarp * HEADS + h];
        float m = -1e30f;
        for (int e = beg + lane; e < end; e += 32) {
            float v = g_asrc[g_csr_src[e] * HEADS + h] + ad;
            v = v > 0.f ? v : NEG_SLOPE * v;
            m = fmaxf(m, v);
        }
#pragma unroll
        for (int o = 16; o; o >>= 1) m = fmaxf(m, __shfl_xor_sync(0xFFFFFFFFu, m, o));
        float s = 0.f;
        for (int e = beg + lane; e < end; e += 32) {
            float v = g_asrc[g_csr_src[e] * HEADS + h] + ad;
            v = v > 0.f ? v : NEG_SLOPE * v;
            s += expf(v - m);
        }
#pragma unroll
        for (int o = 16; o; o >>= 1) s += __shfl_xor_sync(0xFFFFFFFFu, s, o);
        float inv = 1.f / (s + EPS_F);
        for (int e = beg + lane; e < end; e += 32) {
            float v = g_asrc[g_csr_src[e] * HEADS + h] + ad;
            v = v > 0.f ? v : NEG_SLOPE * v;
            g_alpha[(size_t)e * HEADS + h] = expf(v - m) * inv;
        }
    }
}

/* -------- aggregation (gather per dst) -> bf16 hi/lo split output -------- */
__global__ __launch_bounds__(512) void k_agg() {
    int n = blockIdx.x;
    int t = threadIdx.x;
    float acc[HEADS];
#pragma unroll
    for (int j = 0; j < HEADS; j++) acc[j] = 0.f;
    int beg = g_off[n], end = g_off[n + 1];
    for (int s = beg; s < end; s++) {
        int src = g_csr_src[s];
        const float* hrow = g_h + (size_t)src * HC;
        const float* al = g_alpha + (size_t)s * HEADS;
#pragma unroll
        for (int j = 0; j < HEADS; j++)
            acc[j] += al[j] * hrow[j * OUT_C + t];
    }
#pragma unroll
    for (int j = 0; j < HEADS; j++) {
        float v = acc[j];
        __nv_bfloat16 hi = __float2bfloat16(v);
        size_t o = (size_t)n * HC + j * OUT_C + t;
        g_agghi[o] = hi;
        g_agglo[o] = __float2bfloat16(v - __bfloat162float(hi));
    }
}

/* ---------------------- fused bias2 = b_lin + b_gat @ W_lin ---------------------- */
__global__ void k_bias2(const float* __restrict__ b_gat,
                        const float* __restrict__ W_lin) {
    int t = threadIdx.x;
    int k0 = blockIdx.x * 128;
    float acc = 0.f;
    for (int k = k0; k < k0 + 128; k++)
        acc += b_gat[k] * W_lin[(size_t)k * LIN_OUT + t];
    atomicAdd(&g_bias2[t], acc);
}

/* ---------------------------- launch ---------------------------- */
extern "C" void kernel_launch(void* const* d_in, const int* in_sizes, int n_in,
                              void* d_out, int out_size) {
    const float* x       = (const float*)d_in[0];
    const int*   ei32    = (const int*)d_in[1];
    const float* W_gat   = (const float*)d_in[2];
    const float* b_gat   = (const float*)d_in[3];
    const float* att_src = (const float*)d_in[4];
    const float* att_dst = (const float*)d_in[5];
    const float* W_lin   = (const float*)d_in[6];
    const float* b_lin   = (const float*)d_in[7];
    float* out = (float*)d_out;

    cudaFuncSetAttribute(hmma_gemm<0>, cudaFuncAttributeMaxDynamicSharedMemorySize,
                         NSTAGE * STAGE_B);
    cudaFuncSetAttribute(hmma_gemm<1>, cudaFuncAttributeMaxDynamicSharedMemorySize,
                         NSTAGE * STAGE_B);

    /* order keeps hmma_gemm<0> at launch idx 3 (profiler capture slot) */
    k_detect<<<1, 64>>>(ei32);
    k_split_x<<<(M_PAD * IN_C + 255) / 256, 256>>>(x);
    { dim3 g(HC / 32, IN_C / 32), b(32, 8); k_splitT<0><<<g, b>>>(W_gat); }
    { dim3 grid(HC / 128, M_PAD / 128);
      hmma_gemm<0><<<grid, 256, NSTAGE * STAGE_B>>>(nullptr); }

    k_init<<<(N_NODES + 255) / 256, 256>>>(b_lin);
    k_hist<<<(E_TOT + 255) / 256, 256>>>(ei32);
    k_scan<<<1, 1024>>>();
    k_scatter<<<(E_TOT + 255) / 256, 256>>>(ei32);
    k_bias2<<<32, LIN_OUT>>>(b_gat, W_lin);
    { dim3 g(LIN_OUT / 32, HC / 32), b(32, 8); k_splitT<1><<<g, b>>>(W_lin); }
    k_padagg<<<((M_PAD - N_NODES) * HC + 255) / 256, 256>>>();

    k_att<<<N_NODES, 256>>>(att_src, att_dst);
    k_softmax<<<(N_NODES * 32 + 255) / 256, 256>>>();
    k_agg<<<N_NODES, 512>>>();

    { dim3 grid(LIN_OUT / 128, M_PAD / 128);
      hmma_gemm<1><<<grid, 256, NSTAGE * STAGE_B>>>(out); }
}

// round 12
// speedup vs baseline: 2.1793x; 1.0355x over previous
#include <cuda_runtime.h>
#include <cuda_bf16.h>
#include <math.h>
#include <stdint.h>

#define N_NODES 8000
#define M_PAD   8064                  /* 63 * 128 */
#define N_EDGES 64000
#define E_TOT   (N_EDGES + N_NODES)
#define HEADS   8
#define OUT_C   512
#define HC      (HEADS * OUT_C)       /* 4096 */
#define IN_C    128
#define LIN_OUT 512
#define NEG_SLOPE 0.2f
#define EPS_F   1e-16f
#define KSPLIT  4                     /* split-K factor for GEMM2 */

/* ------------- scratch (static device globals; no allocation) -------------
 * g_h doubles as split-K partial buffer for GEMM2 (dead after k_agg):
 * needs KSPLIT * M_PAD * LIN_OUT floats = 66 MB < 131 MB.  */
__device__ float g_h[(size_t)N_NODES * HC];
__device__ __nv_bfloat16 g_xhi[(size_t)M_PAD * IN_C];
__device__ __nv_bfloat16 g_xlo[(size_t)M_PAD * IN_C];
__device__ __nv_bfloat16 g_wgat_hi[(size_t)HC * IN_C];    /* W_gat^T [4096,128] */
__device__ __nv_bfloat16 g_wgat_lo[(size_t)HC * IN_C];
__device__ __nv_bfloat16 g_agghi[(size_t)M_PAD * HC];
__device__ __nv_bfloat16 g_agglo[(size_t)M_PAD * HC];
__device__ __nv_bfloat16 g_wlin_hi[(size_t)LIN_OUT * HC]; /* W_lin^T [512,4096] */
__device__ __nv_bfloat16 g_wlin_lo[(size_t)LIN_OUT * HC];
__device__ float g_asrc[N_NODES * HEADS];
__device__ float g_adst[N_NODES * HEADS];
__device__ int   g_count[N_NODES];
__device__ int   g_cursor[N_NODES];
__device__ int   g_off[N_NODES + 1];
__device__ int   g_csr_src[E_TOT];
__device__ float g_alpha[(size_t)E_TOT * HEADS];
__device__ float g_bias2[LIN_OUT];
__device__ int   g_is64;

/* ============================ PTX helpers (family-safe) ============================ */
__device__ __forceinline__ uint32_t smem_u32(const void* p) {
    uint32_t a;
    asm("{ .reg .u64 t; cvta.to.shared.u64 t, %1; cvt.u32.u64 %0, t; }"
        : "=r"(a) : "l"(p));
    return a;
}
__device__ __forceinline__ void cp_async16(uint32_t s, const void* g) {
    asm volatile("cp.async.cg.shared.global [%0], [%1], 16;" :: "r"(s), "l"(g));
}
__device__ __forceinline__ void cp_commit() {
    asm volatile("cp.async.commit_group;" ::: "memory");
}
template <int N>
__device__ __forceinline__ void cp_wait() {
    asm volatile("cp.async.wait_group %0;" :: "n"(N) : "memory");
}
__device__ __forceinline__ void ldm_x4(uint32_t addr, uint32_t& r0, uint32_t& r1,
                                       uint32_t& r2, uint32_t& r3) {
    asm volatile("ldmatrix.sync.aligned.m8n8.x4.shared.b16 {%0,%1,%2,%3}, [%4];"
                 : "=r"(r0), "=r"(r1), "=r"(r2), "=r"(r3) : "r"(addr));
}
__device__ __forceinline__ void mma_bf16(float& c0, float& c1, float& c2, float& c3,
                                         uint32_t a0, uint32_t a1, uint32_t a2, uint32_t a3,
                                         uint32_t b0, uint32_t b1) {
    asm volatile(
        "mma.sync.aligned.m16n8k16.row.col.f32.bf16.bf16.f32 "
        "{%0,%1,%2,%3}, {%4,%5,%6,%7}, {%8,%9}, {%0,%1,%2,%3};"
        : "+f"(c0), "+f"(c1), "+f"(c2), "+f"(c3)
        : "r"(a0), "r"(a1), "r"(a2), "r"(a3), "r"(b0), "r"(b1));
}

/* ======================= edge dtype detect / decode ======================= */
__global__ void k_detect(const int* __restrict__ ei32) {
    int lane = threadIdx.x;
    int w = ei32[2 * lane + 1];
    unsigned any = __ballot_sync(0xFFFFFFFFu, w != 0);
    __shared__ int s_any;
    if (threadIdx.x == 0) s_any = 0;
    __syncthreads();
    if (any && (lane & 31) == 0) atomicOr(&s_any, 1);
    __syncthreads();
    if (threadIdx.x == 0) g_is64 = (s_any == 0) ? 1 : 0;
}
__device__ __forceinline__ int edge_decode(const int* ei32, int i, int& src, int& dst) {
    if (i >= N_EDGES) { src = dst = i - N_EDGES; return 1; }
    if (g_is64) { src = ei32[2 * i]; dst = ei32[2 * (N_EDGES + i)]; }
    else        { src = ei32[i];     dst = ei32[N_EDGES + i]; }
    return (src >= 0 && src < N_NODES && dst >= 0 && dst < N_NODES);
}

/* ============================ init / CSR ============================ */
__global__ void k_init(const float* __restrict__ b_lin) {
    int i = blockIdx.x * blockDim.x + threadIdx.x;
    if (i < N_NODES) { g_count[i] = 0; g_cursor[i] = 0; }
    if (i < LIN_OUT) g_bias2[i] = b_lin[i];
}
__global__ void k_hist(const int* __restrict__ ei32) {
    int i = blockIdx.x * blockDim.x + threadIdx.x;
    if (i >= E_TOT) return;
    int src, dst;
    if (edge_decode(ei32, i, src, dst)) atomicAdd(&g_count[dst], 1);
}
__global__ void k_scan() {
    __shared__ int s[1024];
    int tid = threadIdx.x;
    int carry = 0;
    for (int c = 0; c < 8; c++) {
        int idx = c * 1024 + tid;
        int v = (idx < N_NODES) ? g_count[idx] : 0;
        s[tid] = v;
        __syncthreads();
        for (int d = 1; d < 1024; d <<= 1) {
            int t = (tid >= d) ? s[tid - d] : 0;
            __syncthreads();
            s[tid] += t;
            __syncthreads();
        }
        if (idx <= N_NODES) g_off[idx] = carry + s[tid] - v;
        int tot = s[1023];
        __syncthreads();
        carry += tot;
    }
}
__global__ void k_scatter(const int* __restrict__ ei32) {
    int i = blockIdx.x * blockDim.x + threadIdx.x;
    if (i >= E_TOT) return;
    int src, dst;
    if (!edge_decode(ei32, i, src, dst)) return;
    int pos = g_off[dst] + atomicAdd(&g_cursor[dst], 1);
    g_csr_src[pos] = src;
}

/* =================== fp32 -> bf16 hi/lo split kernels =================== */
__global__ void k_split_x(const float* __restrict__ x) {
    int i = blockIdx.x * blockDim.x + threadIdx.x;
    if (i >= M_PAD * IN_C) return;
    float v = (i < N_NODES * IN_C) ? x[i] : 0.f;
    __nv_bfloat16 hi = __float2bfloat16(v);
    g_xhi[i] = hi;
    g_xlo[i] = __float2bfloat16(v - __bfloat162float(hi));
}
template <int WHICH>  /* 0: W_gat, 1: W_lin -- transpose + split */
__global__ void k_splitT(const float* __restrict__ in) {
    constexpr int K = WHICH ? HC : IN_C;
    constexpr int N = WHICH ? LIN_OUT : HC;
    __nv_bfloat16* ohi = WHICH ? g_wlin_hi : g_wgat_hi;
    __nv_bfloat16* olo = WHICH ? g_wlin_lo : g_wgat_lo;
    __shared__ float t[32][33];
    int tx = threadIdx.x, ty = threadIdx.y;
    int n0 = blockIdx.x * 32, k0 = blockIdx.y * 32;
#pragma unroll
    for (int r = 0; r < 4; r++)
        t[ty + 8 * r][tx] = in[(size_t)(k0 + ty + 8 * r) * N + n0 + tx];
    __syncthreads();
#pragma unroll
    for (int r = 0; r < 4; r++) {
        float v = t[tx][ty + 8 * r];
        __nv_bfloat16 hi = __float2bfloat16(v);
        size_t o = (size_t)(n0 + ty + 8 * r) * K + k0 + tx;
        ohi[o] = hi;
        olo[o] = __float2bfloat16(v - __bfloat162float(hi));
    }
}
__global__ void k_padagg() {
    int i = blockIdx.x * blockDim.x + threadIdx.x;
    if (i >= (M_PAD - N_NODES) * HC) return;
    __nv_bfloat16 z = __float2bfloat16(0.f);
    g_agghi[(size_t)N_NODES * HC + i] = z;
    g_agglo[(size_t)N_NODES * HC + i] = z;
}

/* ============ HMMA GEMM, fused split-3 (single K-sweep, fp32 acc) ============
 * Per K-chunk (BK=32): load all four tiles (Ahi,Alo,Bhi,Blo) once, issue
 * hi*hi + hi*lo + lo*hi into the same fp32 accumulators.
 * 2-stage cp.async pipeline, 80 KB smem -> 2 CTAs/SM.
 * MODE 0: g_h = x @ W_gat^T                     (Ktot=128,  Ntot=4096)
 * MODE 1: split-K x4 partials -> g_h scratch     (Ktot=4096, Ntot=512)
 *         blockIdx.z selects K range; k_reduce sums partials + bias. */
#define BK       32
#define SSTRIDE  40                    /* bf16 per smem row: 32 + 8 pad (80 B) */
#define TILE_B   (128 * SSTRIDE * 2)   /* 10240 B per tile */
#define STAGE_B  (4 * TILE_B)          /* 40960 B per stage */
#define NSTAGE   2
template <int MODE>
__global__ __launch_bounds__(256, 2)
void hmma_gemm(float* __restrict__ CoutParam) {
    constexpr int Ktot = MODE ? HC : IN_C;
    constexpr int Ntot = MODE ? LIN_OUT : HC;
    constexpr int KCP = MODE ? (Ktot / BK / KSPLIT) : (Ktot / BK);

    const __nv_bfloat16 *Ah, *Al, *Bh, *Bl;
    if (MODE == 0) { Ah = g_xhi;  Al = g_xlo;  Bh = g_wgat_hi; Bl = g_wgat_lo; }
    else           { Ah = g_agghi; Al = g_agglo; Bh = g_wlin_hi; Bl = g_wlin_lo; }

    int kz = MODE ? blockIdx.z : 0;
    size_t kbase = (size_t)kz * KCP * BK;
    /* MODE 0 writes g_h as result; MODE 1 writes g_h as split-K partials */
    float* Cout = (MODE == 0) ? (float*)g_h
                              : (float*)g_h + (size_t)kz * M_PAD * LIN_OUT;
    (void)CoutParam;

    extern __shared__ __align__(16) uint8_t dsm[];

    int tid = threadIdx.x, lane = tid & 31, wid = tid >> 5;
    int wm = wid >> 2, wn = wid & 3;          /* warp grid 2 x 4 */
    int m0 = blockIdx.y * 128, n0 = blockIdx.x * 128;

    int r0c = tid >> 2, f = tid & 3;
    uint32_t dst_off0 = (uint32_t)(r0c * (SSTRIDE * 2) + f * 16);
    uint32_t dst_off1 = dst_off0 + 64 * (SSTRIDE * 2);

    auto issue_load = [&](int cc, int st) {
        size_t koff = kbase + (size_t)cc * BK + f * 8;
        uint8_t* base = dsm + st * STAGE_B;
        uint32_t s0 = smem_u32(base);
        cp_async16(s0 + 0 * TILE_B + dst_off0, Ah + (size_t)(m0 + r0c) * Ktot + koff);
        cp_async16(s0 + 0 * TILE_B + dst_off1, Ah + (size_t)(m0 + r0c + 64) * Ktot + koff);
        cp_async16(s0 + 1 * TILE_B + dst_off0, Al + (size_t)(m0 + r0c) * Ktot + koff);
        cp_async16(s0 + 1 * TILE_B + dst_off1, Al + (size_t)(m0 + r0c + 64) * Ktot + koff);
        cp_async16(s0 + 2 * TILE_B + dst_off0, Bh + (size_t)(n0 + r0c) * Ktot + koff);
        cp_async16(s0 + 2 * TILE_B + dst_off1, Bh + (size_t)(n0 + r0c + 64) * Ktot + koff);
        cp_async16(s0 + 3 * TILE_B + dst_off0, Bl + (size_t)(n0 + r0c) * Ktot + koff);
        cp_async16(s0 + 3 * TILE_B + dst_off1, Bl + (size_t)(n0 + r0c + 64) * Ktot + koff);
        cp_commit();
    };

    float acc[4][4][4];
#pragma unroll
    for (int i = 0; i < 4; i++)
#pragma unroll
        for (int j = 0; j < 4; j++)
#pragma unroll
            for (int k = 0; k < 4; k++) acc[i][j][k] = 0.f;

    int a_row = (lane & 7) + ((lane >> 3) & 1) * 8;
    int a_col = ((lane >> 4) & 1) * 8;
    int b_row = (lane & 7) + ((lane >> 4) & 1) * 8;
    int b_col = ((lane >> 3) & 1) * 8;

    issue_load(0, 0);
    if (KCP > 1) issue_load(1, 1);

    for (int cc = 0; cc < KCP; cc++) {
        int st = cc & 1;
        if (cc + 1 < KCP) cp_wait<1>(); else cp_wait<0>();
        __syncthreads();

        const __nv_bfloat16* sAh = (const __nv_bfloat16*)(dsm + st * STAGE_B + 0 * TILE_B);
        const __nv_bfloat16* sAl = (const __nv_bfloat16*)(dsm + st * STAGE_B + 1 * TILE_B);
        const __nv_bfloat16* sBh = (const __nv_bfloat16*)(dsm + st * STAGE_B + 2 * TILE_B);
        const __nv_bfloat16* sBl = (const __nv_bfloat16*)(dsm + st * STAGE_B + 3 * TILE_B);

#pragma unroll
        for (int kk = 0; kk < 2; kk++) {
            uint32_t ah[4][4], al[4][4], bh[4][2], bl[4][2];
#pragma unroll
            for (int mt = 0; mt < 4; mt++) {
                int roff = (wm * 64 + mt * 16 + a_row) * SSTRIDE + kk * 16 + a_col;
                ldm_x4(smem_u32(sAh + roff), ah[mt][0], ah[mt][1], ah[mt][2], ah[mt][3]);
                ldm_x4(smem_u32(sAl + roff), al[mt][0], al[mt][1], al[mt][2], al[mt][3]);
            }
#pragma unroll
            for (int np = 0; np < 2; np++) {
                int roff = (wn * 32 + np * 16 + b_row) * SSTRIDE + kk * 16 + b_col;
                uint32_t r0, r1, r2, r3;
                ldm_x4(smem_u32(sBh + roff), r0, r1, r2, r3);
                bh[np * 2][0] = r0; bh[np * 2][1] = r1;
                bh[np * 2 + 1][0] = r2; bh[np * 2 + 1][1] = r3;
                ldm_x4(smem_u32(sBl + roff), r0, r1, r2, r3);
                bl[np * 2][0] = r0; bl[np * 2][1] = r1;
                bl[np * 2 + 1][0] = r2; bl[np * 2 + 1][1] = r3;
            }
#pragma unroll
            for (int mt = 0; mt < 4; mt++)
#pragma unroll
                for (int nt = 0; nt < 4; nt++) {
                    mma_bf16(acc[mt][nt][0], acc[mt][nt][1], acc[mt][nt][2], acc[mt][nt][3],
                             ah[mt][0], ah[mt][1], ah[mt][2], ah[mt][3],
                             bh[nt][0], bh[nt][1]);
                    mma_bf16(acc[mt][nt][0], acc[mt][nt][1], acc[mt][nt][2], acc[mt][nt][3],
                             ah[mt][0], ah[mt][1], ah[mt][2], ah[mt][3],
                             bl[nt][0], bl[nt][1]);
                    mma_bf16(acc[mt][nt][0], acc[mt][nt][1], acc[mt][nt][2], acc[mt][nt][3],
                             al[mt][0], al[mt][1], al[mt][2], al[mt][3],
                             bh[nt][0], bh[nt][1]);
                }
        }
        __syncthreads();
        if (cc + 2 < KCP) issue_load(cc + 2, st);
    }

    /* epilogue: MODE 0 guards rows to N_NODES; MODE 1 writes full partial tile */
    int lrow = lane >> 2, lcol = (lane & 3) * 2;
#pragma unroll
    for (int mt = 0; mt < 4; mt++) {
        int r = m0 + wm * 64 + mt * 16 + lrow;
#pragma unroll
        for (int half = 0; half < 2; half++) {
            int rr = r + half * 8;
            if (MODE == 1 || rr < N_NODES) {
                float* cp = Cout + (size_t)rr * Ntot;
#pragma unroll
                for (int nt = 0; nt < 4; nt++) {
                    int cbase = n0 + wn * 32 + nt * 8 + lcol;
                    cp[cbase] = acc[mt][nt][half * 2];
                    cp[cbase + 1] = acc[mt][nt][half * 2 + 1];
                }
            }
        }
    }
}

/* -------- split-K reduce: out = sum_z partial[z] + bias2 (float4) -------- */
__global__ void k_reduce(float* __restrict__ out) {
    int i = blockIdx.x * blockDim.x + threadIdx.x;
    if (i >= N_NODES * LIN_OUT / 4) return;
    const float4* p = (const float4*)g_h;
    size_t stride4 = (size_t)M_PAD * LIN_OUT / 4;
    float4 a = p[i];
    float4 b = p[i + stride4];
    float4 c = p[i + 2 * stride4];
    float4 d = p[i + 3 * stride4];
    int col = (i * 4) & (LIN_OUT - 1);
    float4 bias = *(const float4*)&g_bias2[col];
    float4 r;
    r.x = a.x + b.x + c.x + d.x + bias.x;
    r.y = a.y + b.y + c.y + d.y + bias.y;
    r.z = a.z + b.z + c.z + d.z + bias.z;
    r.w = a.w + b.w + c.w + d.w + bias.w;
    ((float4*)out)[i] = r;
}

/* ---------------------- per-node attention logits ---------------------- */
__global__ void k_att(const float* __restrict__ att_src,
                      const float* __restrict__ att_dst) {
    int n = blockIdx.x;
    int w = threadIdx.x >> 5;
    int lane = threadIdx.x & 31;
    const float* hrow = g_h + (size_t)n * HC + w * OUT_C;
    const float* as = att_src + w * OUT_C;
    const float* ad = att_dst + w * OUT_C;
    float s = 0.f, d = 0.f;
    for (int c = lane; c < OUT_C; c += 32) {
        float hv = hrow[c];
        s += hv * as[c];
        d += hv * ad[c];
    }
#pragma unroll
    for (int o = 16; o; o >>= 1) {
        s += __shfl_xor_sync(0xFFFFFFFFu, s, o);
        d += __shfl_xor_sync(0xFFFFFFFFu, d, o);
    }
    if (lane == 0) {
        g_asrc[n * HEADS + w] = s;
        g_adst[n * HEADS + w] = d;
    }
}

/* ---------------------- edge softmax (one warp per dst) ---------------------- */
__global__ void k_softmax() {
    int gwarp = (blockIdx.x * blockDim.x + threadIdx.x) >> 5;
    int lane = threadIdx.x & 31;
    if (gwarp >= N_NODES) return;
    int beg = g_off[gwarp], end = g_off[gwarp + 1];
    for (int h = 0; h < HEADS; h++) {
        float ad = g_adst[gwarp * HEADS + h];
        float m = -1e30f;
        for (int e = beg + lane; e < end; e += 32) {
            float v = g_asrc[g_csr_src[e] * HEADS + h] + ad;
            v = v > 0.f ? v : NEG_SLOPE * v;
            m = fmaxf(m, v);
        }
#pragma unroll
        for (int o = 16; o; o >>= 1) m = fmaxf(m, __shfl_xor_sync(0xFFFFFFFFu, m, o));
        float s = 0.f;
        for (int e = beg + lane; e < end; e += 32) {
            float v = g_asrc[g_csr_src[e] * HEADS + h] + ad;
            v = v > 0.f ? v : NEG_SLOPE * v;
            s += expf(v - m);
        }
#pragma unroll
        for (int o = 16; o; o >>= 1) s += __shfl_xor_sync(0xFFFFFFFFu, s, o);
        float inv = 1.f / (s + EPS_F);
        for (int e = beg + lane; e < end; e += 32) {
            float v = g_asrc[g_csr_src[e] * HEADS + h] + ad;
            v = v > 0.f ? v : NEG_SLOPE * v;
            g_alpha[(size_t)e * HEADS + h] = expf(v - m) * inv;
        }
    }
}

/* -------- aggregation (gather per dst) -> bf16 hi/lo split output -------- */
__global__ __launch_bounds__(512) void k_agg() {
    int n = blockIdx.x;
    int t = threadIdx.x;
    float acc[HEADS];
#pragma unroll
    for (int j = 0; j < HEADS; j++) acc[j] = 0.f;
    int beg = g_off[n], end = g_off[n + 1];
    for (int s = beg; s < end; s++) {
        int src = g_csr_src[s];
        const float* hrow = g_h + (size_t)src * HC;
        const float* al = g_alpha + (size_t)s * HEADS;
#pragma unroll
        for (int j = 0; j < HEADS; j++)
            acc[j] += al[j] * hrow[j * OUT_C + t];
    }
#pragma unroll
    for (int j = 0; j < HEADS; j++) {
        float v = acc[j];
        __nv_bfloat16 hi = __float2bfloat16(v);
        size_t o = (size_t)n * HC + j * OUT_C + t;
        g_agghi[o] = hi;
        g_agglo[o] = __float2bfloat16(v - __bfloat162float(hi));
    }
}

/* ---------------------- fused bias2 = b_lin + b_gat @ W_lin ---------------------- */
__global__ void k_bias2(const float* __restrict__ b_gat,
                        const float* __restrict__ W_lin) {
    int t = threadIdx.x;
    int k0 = blockIdx.x * 128;
    float acc = 0.f;
    for (int k = k0; k < k0 + 128; k++)
        acc += b_gat[k] * W_lin[(size_t)k * LIN_OUT + t];
    atomicAdd(&g_bias2[t], acc);
}

/* ---------------------------- launch ---------------------------- */
extern "C" void kernel_launch(void* const* d_in, const int* in_sizes, int n_in,
                              void* d_out, int out_size) {
    const float* x       = (const float*)d_in[0];
    const int*   ei32    = (const int*)d_in[1];
    const float* W_gat   = (const float*)d_in[2];
    const float* b_gat   = (const float*)d_in[3];
    const float* att_src = (const float*)d_in[4];
    const float* att_dst = (const float*)d_in[5];
    const float* W_lin   = (const float*)d_in[6];
    const float* b_lin   = (const float*)d_in[7];
    float* out = (float*)d_out;

    cudaFuncSetAttribute(hmma_gemm<0>, cudaFuncAttributeMaxDynamicSharedMemorySize,
                         NSTAGE * STAGE_B);
    cudaFuncSetAttribute(hmma_gemm<1>, cudaFuncAttributeMaxDynamicSharedMemorySize,
                         NSTAGE * STAGE_B);

    /* order keeps hmma_gemm<0> at launch idx 3 (profiler capture slot) */
    k_detect<<<1, 64>>>(ei32);
    k_split_x<<<(M_PAD * IN_C + 255) / 256, 256>>>(x);
    { dim3 g(HC / 32, IN_C / 32), b(32, 8); k_splitT<0><<<g, b>>>(W_gat); }
    { dim3 grid(HC / 128, M_PAD / 128);
      hmma_gemm<0><<<grid, 256, NSTAGE * STAGE_B>>>(nullptr); }

    k_init<<<(N_NODES + 255) / 256, 256>>>(b_lin);
    k_hist<<<(E_TOT + 255) / 256, 256>>>(ei32);
    k_scan<<<1, 1024>>>();
    k_scatter<<<(E_TOT + 255) / 256, 256>>>(ei32);
    k_bias2<<<32, LIN_OUT>>>(b_gat, W_lin);
    { dim3 g(LIN_OUT / 32, HC / 32), b(32, 8); k_splitT<1><<<g, b>>>(W_lin); }
    k_padagg<<<((M_PAD - N_NODES) * HC + 255) / 256, 256>>>();

    k_att<<<N_NODES, 256>>>(att_src, att_dst);
    k_softmax<<<(N_NODES * 32 + 255) / 256, 256>>>();
    k_agg<<<N_NODES, 512>>>();

    /* GEMM2 split-K x4 -> partials in g_h scratch, then reduce (+bias) */
    { dim3 grid(LIN_OUT / 128, M_PAD / 128, KSPLIT);
      hmma_gemm<1><<<grid, 256, NSTAGE * STAGE_B>>>(nullptr); }
    k_reduce<<<(N_NODES * LIN_OUT / 4 + 255) / 256, 256>>>(out);
}